// round 4
// baseline (speedup 1.0000x reference)
#include <cuda_runtime.h>
#include <math.h>

#define BB 2
#define TT 2048
#define DD 1024
#define HH 16
#define HD 64
#define MROWS (BB*TT)   // 4096

// Scratch (allocation-free rule: device globals)
__device__ float g_q[BB*HH*TT*HD];   // [b][h][t][hd]
__device__ float g_k[BB*HH*TT*HD];
__device__ float g_v[BB*HH*TT*HD];
__device__ float g_y[BB*TT*DD];      // [b][t][h*64+hd]

#define NEG_INF __int_as_float(0xff800000)

// ---------------------------------------------------------------------------
// 128x128x8 register-blocked SGEMM, 256 threads, 8x8 per thread.
// MODE 0: C = X @ W_qkv + b, scattered into g_q/g_k/g_v [B,H,T,HD]
// MODE 1: C = g_y @ W_o + b, plain row-major output
// ---------------------------------------------------------------------------
template<int MODE>
__global__ __launch_bounds__(256)
void sgemm_kernel(const float* __restrict__ A, const float* __restrict__ B,
                  const float* __restrict__ bias, float* __restrict__ C, int N)
{
    const int K = DD;
    __shared__ float As[8][128];
    __shared__ float Bs[8][128];

    const int tid = threadIdx.x;
    const int bm = blockIdx.y * 128;
    const int bn = blockIdx.x * 128;

    const int arow = tid >> 1;
    const int acol = (tid & 1) << 2;
    const int brow = tid >> 5;
    const int bcol = (tid & 31) << 2;

    const float* Aeff = (MODE == 0) ? A : (const float*)g_y;
    const float* Ap = Aeff + (size_t)(bm + arow) * K + acol;
    const float* Bp = B + (size_t)brow * N + bn + bcol;

    const int tx = tid & 15;
    const int ty = tid >> 4;

    float acc[8][8];
#pragma unroll
    for (int i = 0; i < 8; i++)
#pragma unroll
        for (int j = 0; j < 8; j++) acc[i][j] = 0.f;

    for (int k0 = 0; k0 < K; k0 += 8) {
        float4 av = *(const float4*)Ap;
        float4 bv = *(const float4*)Bp;
        As[acol + 0][arow] = av.x;
        As[acol + 1][arow] = av.y;
        As[acol + 2][arow] = av.z;
        As[acol + 3][arow] = av.w;
        *(float4*)(&Bs[brow][bcol]) = bv;
        __syncthreads();
#pragma unroll
        for (int k = 0; k < 8; k++) {
            float ar[8], br[8];
            *(float4*)(ar)     = *(const float4*)(&As[k][ty * 8]);
            *(float4*)(ar + 4) = *(const float4*)(&As[k][ty * 8 + 4]);
            *(float4*)(br)     = *(const float4*)(&Bs[k][tx * 8]);
            *(float4*)(br + 4) = *(const float4*)(&Bs[k][tx * 8 + 4]);
#pragma unroll
            for (int i = 0; i < 8; i++)
#pragma unroll
                for (int j = 0; j < 8; j++)
                    acc[i][j] = fmaf(ar[i], br[j], acc[i][j]);
        }
        __syncthreads();
        Ap += 8;
        Bp += (size_t)8 * N;
    }

    const int colbase = bn + tx * 8;
    if (MODE == 0) {
        // scatter into q/k/v [b][h][t][hd]; 8 contiguous cols stay within one head
        const int part = colbase >> 10;
        const int rem  = colbase & 1023;
        const int h    = rem >> 6;
        const int hd0  = rem & 63;
        float* dbase = (part == 0) ? g_q : ((part == 1) ? g_k : g_v);
#pragma unroll
        for (int i = 0; i < 8; i++) {
            const int row = bm + ty * 8 + i;
            const int b = row >> 11;        // row / TT
            const int t = row & (TT - 1);
            float* dst = dbase + ((size_t)((b * HH + h) * TT + t)) * HD + hd0;
            float out[8];
#pragma unroll
            for (int j = 0; j < 8; j++) out[j] = acc[i][j] + bias[colbase + j];
            *(float4*)(dst)     = *(float4*)(out);
            *(float4*)(dst + 4) = *(float4*)(out + 4);
        }
    } else {
#pragma unroll
        for (int i = 0; i < 8; i++) {
            const int row = bm + ty * 8 + i;
            float out[8];
#pragma unroll
            for (int j = 0; j < 8; j++) out[j] = acc[i][j] + bias[colbase + j];
            float* dst = C + (size_t)row * N + colbase;
            *(float4*)(dst)     = *(float4*)(out);
            *(float4*)(dst + 4) = *(float4*)(out + 4);
        }
    }
}

// ---------------------------------------------------------------------------
// Flash attention: one block per (64-query tile, b*h). 128 threads.
// Thread (tx=tid&15, ty=tid>>4): owns S rows ty*8+i (i<8), cols tx+16*j (j<4),
// and O rows ty*8+i, dims tx+16*j.
// Smem: Qs[d][r] (transposed), KP[d][c] for K then reused as P[c][r], Vs[c][d].
// ---------------------------------------------------------------------------
__global__ __launch_bounds__(128)
void flash_kernel()
{
    __shared__ float Qs[64][68];  // [d][r]
    __shared__ float KP[64][68];  // K: [d][c]  /  P: [c][r]
    __shared__ float Vs[64][68];  // [c][d]

    const int tid = threadIdx.x;
    const int tx = tid & 15;
    const int ty = tid >> 4;
    const int qi = blockIdx.x;    // query tile 0..31
    const int bh = blockIdx.y;    // 0..31 == b*HH + h
    const int b = bh >> 4;
    const int h = bh & 15;

    const float* qg = g_q + (size_t)bh * TT * HD;
    const float* kg = g_k + (size_t)bh * TT * HD;
    const float* vg = g_v + (size_t)bh * TT * HD;

    // Load Q tile transposed: Qs[d][r]
    for (int u = tid; u < 64 * 16; u += 128) {
        const int r  = u >> 4;
        const int c4 = (u & 15) << 2;
        float4 v = *(const float4*)(qg + ((size_t)(qi * 64 + r)) * HD + c4);
        Qs[c4 + 0][r] = v.x;
        Qs[c4 + 1][r] = v.y;
        Qs[c4 + 2][r] = v.z;
        Qs[c4 + 3][r] = v.w;
    }

    float m[8], l[8], O[8][4];
#pragma unroll
    for (int i = 0; i < 8; i++) {
        m[i] = NEG_INF;
        l[i] = 0.f;
#pragma unroll
        for (int j = 0; j < 4; j++) O[i][j] = 0.f;
    }

    const float scale = 0.03125f;  // 1/sqrt(1024)

    for (int kb = 0; kb <= qi; kb++) {
        __syncthreads();  // prior PV reads of KP/Vs done (and Q stores on iter 0)
        // Load K (transposed into KP[d][c]) and V (Vs[c][d])
        for (int u = tid; u < 64 * 16; u += 128) {
            const int r  = u >> 4;
            const int c4 = (u & 15) << 2;
            const size_t goff = ((size_t)(kb * 64 + r)) * HD + c4;
            float4 kv = *(const float4*)(kg + goff);
            KP[c4 + 0][r] = kv.x;
            KP[c4 + 1][r] = kv.y;
            KP[c4 + 2][r] = kv.z;
            KP[c4 + 3][r] = kv.w;
            float4 vv = *(const float4*)(vg + goff);
            *(float4*)(&Vs[r][c4]) = vv;
        }
        __syncthreads();

        // S = Q K^T
        float s[8][4];
#pragma unroll
        for (int i = 0; i < 8; i++)
#pragma unroll
            for (int j = 0; j < 4; j++) s[i][j] = 0.f;

#pragma unroll 4
        for (int d = 0; d < 64; d++) {
            float qf[8], kf[4];
            *(float4*)(qf)     = *(const float4*)(&Qs[d][ty * 8]);
            *(float4*)(qf + 4) = *(const float4*)(&Qs[d][ty * 8 + 4]);
            kf[0] = KP[d][tx];
            kf[1] = KP[d][tx + 16];
            kf[2] = KP[d][tx + 32];
            kf[3] = KP[d][tx + 48];
#pragma unroll
            for (int i = 0; i < 8; i++)
#pragma unroll
                for (int j = 0; j < 4; j++)
                    s[i][j] = fmaf(qf[i], kf[j], s[i][j]);
        }

        const bool diag = (kb == qi);
#pragma unroll
        for (int i = 0; i < 8; i++) {
#pragma unroll
            for (int j = 0; j < 4; j++) {
                float sv = s[i][j] * scale;
                if (diag && (tx + 16 * j) > (ty * 8 + i)) sv = NEG_INF;
                s[i][j] = sv;
            }
        }

        // online softmax update per row
#pragma unroll
        for (int i = 0; i < 8; i++) {
            float rm = fmaxf(fmaxf(s[i][0], s[i][1]), fmaxf(s[i][2], s[i][3]));
            rm = fmaxf(rm, __shfl_xor_sync(0xffffffffu, rm, 1));
            rm = fmaxf(rm, __shfl_xor_sync(0xffffffffu, rm, 2));
            rm = fmaxf(rm, __shfl_xor_sync(0xffffffffu, rm, 4));
            rm = fmaxf(rm, __shfl_xor_sync(0xffffffffu, rm, 8));
            const float mn = fmaxf(m[i], rm);
            const float corr = __expf(m[i] - mn);
            m[i] = mn;
            float rs = 0.f;
#pragma unroll
            for (int j = 0; j < 4; j++) {
                const float p = __expf(s[i][j] - mn);
                s[i][j] = p;
                rs += p;
            }
            rs += __shfl_xor_sync(0xffffffffu, rs, 1);
            rs += __shfl_xor_sync(0xffffffffu, rs, 2);
            rs += __shfl_xor_sync(0xffffffffu, rs, 4);
            rs += __shfl_xor_sync(0xffffffffu, rs, 8);
            l[i] = l[i] * corr + rs;
#pragma unroll
            for (int j = 0; j < 4; j++) O[i][j] *= corr;
        }

        __syncthreads();  // everyone done reading KP as K
        // write P transposed: KP[c][r]
#pragma unroll
        for (int i = 0; i < 8; i++)
#pragma unroll
            for (int j = 0; j < 4; j++)
                KP[tx + 16 * j][ty * 8 + i] = s[i][j];
        __syncthreads();

        // O += P V
#pragma unroll 4
        for (int c = 0; c < 64; c++) {
            float pf[8], vf[4];
            *(float4*)(pf)     = *(const float4*)(&KP[c][ty * 8]);
            *(float4*)(pf + 4) = *(const float4*)(&KP[c][ty * 8 + 4]);
            vf[0] = Vs[c][tx];
            vf[1] = Vs[c][tx + 16];
            vf[2] = Vs[c][tx + 32];
            vf[3] = Vs[c][tx + 48];
#pragma unroll
            for (int i = 0; i < 8; i++)
#pragma unroll
                for (int j = 0; j < 4; j++)
                    O[i][j] = fmaf(pf[i], vf[j], O[i][j]);
        }
    }

    // write O / l into g_y [b][t][h*64+hd]
#pragma unroll
    for (int i = 0; i < 8; i++) {
        const float inv = 1.f / l[i];
        const int t = qi * 64 + ty * 8 + i;
        float* dst = g_y + ((size_t)(b * TT + t)) * DD + h * 64;
        dst[tx]      = O[i][0] * inv;
        dst[tx + 16] = O[i][1] * inv;
        dst[tx + 32] = O[i][2] * inv;
        dst[tx + 48] = O[i][3] * inv;
    }
}

// ---------------------------------------------------------------------------
extern "C" void kernel_launch(void* const* d_in, const int* in_sizes, int n_in,
                              void* d_out, int out_size)
{
    const float* x     = (const float*)d_in[0];
    const float* w_qkv = (const float*)d_in[1];
    const float* b_qkv = (const float*)d_in[2];
    const float* w_o   = (const float*)d_in[3];
    const float* b_o   = (const float*)d_in[4];
    float* out = (float*)d_out;

    // QKV projection: [4096,1024] @ [1024,3072] -> scatter to q/k/v
    {
        dim3 grid(3 * DD / 128, MROWS / 128);  // (24, 32)
        sgemm_kernel<0><<<grid, 256>>>(x, w_qkv, b_qkv, nullptr, 3 * DD);
    }
    // Flash attention
    {
        dim3 grid(TT / 64, BB * HH);           // (32, 32)
        flash_kernel<<<grid, 128>>>();
    }
    // Output projection: [4096,1024] @ [1024,1024] + b_o
    {
        dim3 grid(DD / 128, MROWS / 128);      // (8, 32)
        sgemm_kernel<1><<<grid, 256>>>(nullptr, w_o, b_o, out, DD);
    }
}

// round 7
// speedup vs baseline: 1.7497x; 1.7497x over previous
#include <cuda_runtime.h>
#include <math.h>
#include <stdint.h>

#define BB 2
#define TT 2048
#define DD 1024
#define HH 16
#define HD 64
#define MROWS (BB*TT)   // 4096

// Scratch (allocation-free rule: device globals)
__device__ float g_q[BB*HH*TT*HD];   // [b][h][t][hd]
__device__ float g_k[BB*HH*TT*HD];
__device__ float g_v[BB*HH*TT*HD];
__device__ float g_y[BB*TT*DD];      // [b][t][h*64+hd]  (tf32-rounded)
__device__ float g_xr[MROWS*DD];     // tf32-rounded x
__device__ float g_wqkvT[3*DD*DD];   // [3D][D] transposed+rounded w_qkv
__device__ float g_woT[DD*DD];       // [D][D] transposed+rounded w_o

#define NEG_INF __int_as_float(0xff800000)

__device__ __forceinline__ float rtf32(float x) {
    uint32_t u;
    asm("cvt.rna.tf32.f32 %0, %1;" : "=r"(u) : "f"(x));
    return __uint_as_float(u);
}

__device__ __forceinline__ unsigned smem_u32(const void* p) {
    return (unsigned)__cvta_generic_to_shared(p);
}

// ---------------------------------------------------------------------------
// Prep: round x to tf32 into g_xr
// ---------------------------------------------------------------------------
__global__ __launch_bounds__(256)
void round_x_kernel(const float* __restrict__ x)
{
    int i = (blockIdx.x * 256 + threadIdx.x) * 4;
    float4 v = *(const float4*)(x + i);
    v.x = rtf32(v.x); v.y = rtf32(v.y); v.z = rtf32(v.z); v.w = rtf32(v.w);
    *(float4*)(g_xr + i) = v;
}

// ---------------------------------------------------------------------------
// Prep: transpose + round weights. dst[c][r] = rtf32(src[r][c]), src is RxC.
// WHICH 0: dst = g_wqkvT (src 1024x3072), WHICH 1: dst = g_woT (src 1024x1024)
// ---------------------------------------------------------------------------
template<int WHICH>
__global__ __launch_bounds__(256)
void transpose_round_kernel(const float* __restrict__ src, int R, int C)
{
    float* dst = (WHICH == 0) ? g_wqkvT : g_woT;
    __shared__ float tile[32][33];
    const int r0 = blockIdx.y * 32, c0 = blockIdx.x * 32;
    const int tx = threadIdx.x & 31, ty = threadIdx.x >> 5;  // ty 0..7
#pragma unroll
    for (int i = 0; i < 32; i += 8)
        tile[ty + i][tx] = src[(size_t)(r0 + ty + i) * C + c0 + tx];
    __syncthreads();
#pragma unroll
    for (int i = 0; i < 32; i += 8)
        dst[(size_t)(c0 + ty + i) * R + r0 + tx] = rtf32(tile[tx][ty + i]);
}

// ---------------------------------------------------------------------------
// TF32 tensor-core GEMM: C[M,N] = A[M,K] @ Bt[N,K]^T + bias
// 128x128x32 block tile, 256 threads (8 warps, 64x32 warp tiles),
// cp.async double-buffered smem, ldmatrix fragment loads, m16n8k8 tf32 mma.
// MODE 0: A = g_xr, Bt = g_wqkvT, scatter into g_q/g_k/g_v [B,H,T,HD]
// MODE 1: A = g_y,  Bt = g_woT,  plain row-major C
// ---------------------------------------------------------------------------
#define SROW 36          // smem row stride in floats (16B-aligned, conflict-free)
#define SBUF (128*SROW)  // 4608 floats per buffer

template<int MODE>
__global__ __launch_bounds__(256, 2)
void gemm_tf32(const float* __restrict__ bias, float* __restrict__ C, int N)
{
    extern __shared__ float sm[];
    float* Asm = sm;              // 2 buffers
    float* Bsm = sm + 2 * SBUF;   // 2 buffers
    const int K = DD;

    const int tid  = threadIdx.x;
    const int lane = tid & 31, warp = tid >> 5;
    const int wm = warp >> 2;     // 0..1
    const int wn = warp & 3;      // 0..3
    const int bm = blockIdx.y * 128, bn = blockIdx.x * 128;

    const float* Aeff = (MODE == 0) ? (const float*)g_xr : (const float*)g_y;
    const float* Bt   = (MODE == 0) ? (const float*)g_wqkvT : (const float*)g_woT;

    float acc[4][4][4];
#pragma unroll
    for (int a = 0; a < 4; a++)
#pragma unroll
        for (int b = 0; b < 4; b++)
#pragma unroll
            for (int c = 0; c < 4; c++) acc[a][b][c] = 0.f;

    const int lm = tid >> 3;      // 0..31 (row within group of 32)
    const int lq = (tid & 7) * 4; // float offset of 16B chunk

    auto copy_chunk = [&](int ck, int buf) {
        const float* ag = Aeff + (size_t)bm * K + ck * 32;
        const float* bg = Bt   + (size_t)bn * K + ck * 32;
        float* as = Asm + buf * SBUF;
        float* bs = Bsm + buf * SBUF;
#pragma unroll
        for (int it = 0; it < 4; it++) {
            const int m = it * 32 + lm;
            unsigned da = smem_u32(as + m * SROW + lq);
            asm volatile("cp.async.cg.shared.global [%0], [%1], 16;\n"
                         :: "r"(da), "l"(ag + (size_t)m * K + lq) : "memory");
            unsigned db = smem_u32(bs + m * SROW + lq);
            asm volatile("cp.async.cg.shared.global [%0], [%1], 16;\n"
                         :: "r"(db), "l"(bg + (size_t)m * K + lq) : "memory");
        }
        asm volatile("cp.async.commit_group;\n" ::: "memory");
    };

    copy_chunk(0, 0);

    const int j8  = lane & 7;
    const int sub = lane >> 3;

    for (int ck = 0; ck < 32; ck++) {
        asm volatile("cp.async.wait_group 0;\n" ::: "memory");
        __syncthreads();
        if (ck + 1 < 32) copy_chunk(ck + 1, (ck + 1) & 1);

        const float* as = Asm + (ck & 1) * SBUF;
        const float* bs = Bsm + (ck & 1) * SBUF;

#pragma unroll
        for (int ks = 0; ks < 4; ks++) {
            const int k8 = ks * 8;
            uint32_t a[4][4];
#pragma unroll
            for (int mf = 0; mf < 4; mf++) {
                const int row = wm * 64 + mf * 16 + (sub & 1) * 8 + j8;
                const int col = k8 + (sub >> 1) * 4;
                unsigned addr = smem_u32(as + row * SROW + col);
                asm volatile("ldmatrix.sync.aligned.m8n8.x4.shared.b16 {%0,%1,%2,%3}, [%4];\n"
                             : "=r"(a[mf][0]), "=r"(a[mf][1]), "=r"(a[mf][2]), "=r"(a[mf][3])
                             : "r"(addr));
            }
            uint32_t b[4][2];
#pragma unroll
            for (int np = 0; np < 2; np++) {  // n-frag pair (2np, 2np+1)
                const int row = wn * 32 + np * 16 + (sub >> 1) * 8 + j8;
                const int col = k8 + (sub & 1) * 4;
                unsigned addr = smem_u32(bs + row * SROW + col);
                asm volatile("ldmatrix.sync.aligned.m8n8.x4.shared.b16 {%0,%1,%2,%3}, [%4];\n"
                             : "=r"(b[2*np][0]), "=r"(b[2*np][1]),
                               "=r"(b[2*np+1][0]), "=r"(b[2*np+1][1])
                             : "r"(addr));
            }
#pragma unroll
            for (int mf = 0; mf < 4; mf++)
#pragma unroll
                for (int nf = 0; nf < 4; nf++)
                    asm volatile(
                        "mma.sync.aligned.m16n8k8.row.col.f32.tf32.tf32.f32 "
                        "{%0,%1,%2,%3}, {%4,%5,%6,%7}, {%8,%9}, {%0,%1,%2,%3};\n"
                        : "+f"(acc[mf][nf][0]), "+f"(acc[mf][nf][1]),
                          "+f"(acc[mf][nf][2]), "+f"(acc[mf][nf][3])
                        : "r"(a[mf][0]), "r"(a[mf][1]), "r"(a[mf][2]), "r"(a[mf][3]),
                          "r"(b[nf][0]), "r"(b[nf][1]));
        }
    }

    // Epilogue
    const int g  = lane >> 2;
    const int tg = lane & 3;
#pragma unroll
    for (int mf = 0; mf < 4; mf++) {
#pragma unroll
        for (int nf = 0; nf < 4; nf++) {
            const int col  = bn + wn * 32 + nf * 8 + 2 * tg;
            const float b0 = bias[col], b1 = bias[col + 1];
            const int row0 = bm + wm * 64 + mf * 16 + g;
            float v00 = acc[mf][nf][0] + b0, v01 = acc[mf][nf][1] + b1;
            float v10 = acc[mf][nf][2] + b0, v11 = acc[mf][nf][3] + b1;
            if (MODE == 0) {
                const int part = col >> 10;
                const int rem  = col & 1023;
                const int h    = rem >> 6;
                const int hd0  = rem & 63;
                float* dbase = (part == 0) ? g_q : ((part == 1) ? g_k : g_v);
#pragma unroll
                for (int rr = 0; rr < 2; rr++) {
                    const int row = row0 + rr * 8;
                    const int bb = row >> 11;
                    const int t  = row & (TT - 1);
                    float2 v = rr ? make_float2(v10, v11) : make_float2(v00, v01);
                    *(float2*)(dbase + ((size_t)((bb * HH + h) * TT + t)) * HD + hd0) = v;
                }
            } else {
                *(float2*)(C + (size_t)row0 * N + col)       = make_float2(v00, v01);
                *(float2*)(C + (size_t)(row0 + 8) * N + col) = make_float2(v10, v11);
            }
        }
    }
}

// ---------------------------------------------------------------------------
// Flash attention: one block per (64-query tile, b*h). 128 threads. fp32.
// ---------------------------------------------------------------------------
__global__ __launch_bounds__(128)
void flash_kernel()
{
    __shared__ float Qs[64][68];  // [d][r]
    __shared__ float KP[64][68];  // K: [d][c]  /  P: [c][r]
    __shared__ float Vs[64][68];  // [c][d]

    const int tid = threadIdx.x;
    const int tx = tid & 15;
    const int ty = tid >> 4;
    const int qi = blockIdx.x;    // query tile 0..31
    const int bh = blockIdx.y;    // 0..31 == b*HH + h
    const int b = bh >> 4;
    const int h = bh & 15;

    const float* qg = g_q + (size_t)bh * TT * HD;
    const float* kg = g_k + (size_t)bh * TT * HD;
    const float* vg = g_v + (size_t)bh * TT * HD;

    for (int u = tid; u < 64 * 16; u += 128) {
        const int r  = u >> 4;
        const int c4 = (u & 15) << 2;
        float4 v = *(const float4*)(qg + ((size_t)(qi * 64 + r)) * HD + c4);
        Qs[c4 + 0][r] = v.x;
        Qs[c4 + 1][r] = v.y;
        Qs[c4 + 2][r] = v.z;
        Qs[c4 + 3][r] = v.w;
    }

    float m[8], l[8], O[8][4];
#pragma unroll
    for (int i = 0; i < 8; i++) {
        m[i] = NEG_INF;
        l[i] = 0.f;
#pragma unroll
        for (int j = 0; j < 4; j++) O[i][j] = 0.f;
    }

    const float scale = 0.03125f;  // 1/sqrt(1024)

    for (int kb = 0; kb <= qi; kb++) {
        __syncthreads();
        for (int u = tid; u < 64 * 16; u += 128) {
            const int r  = u >> 4;
            const int c4 = (u & 15) << 2;
            const size_t goff = ((size_t)(kb * 64 + r)) * HD + c4;
            float4 kv = *(const float4*)(kg + goff);
            KP[c4 + 0][r] = kv.x;
            KP[c4 + 1][r] = kv.y;
            KP[c4 + 2][r] = kv.z;
            KP[c4 + 3][r] = kv.w;
            float4 vv = *(const float4*)(vg + goff);
            *(float4*)(&Vs[r][c4]) = vv;
        }
        __syncthreads();

        float s[8][4];
#pragma unroll
        for (int i = 0; i < 8; i++)
#pragma unroll
            for (int j = 0; j < 4; j++) s[i][j] = 0.f;

#pragma unroll 4
        for (int d = 0; d < 64; d++) {
            float qf[8], kf[4];
            *(float4*)(qf)     = *(const float4*)(&Qs[d][ty * 8]);
            *(float4*)(qf + 4) = *(const float4*)(&Qs[d][ty * 8 + 4]);
            kf[0] = KP[d][tx];
            kf[1] = KP[d][tx + 16];
            kf[2] = KP[d][tx + 32];
            kf[3] = KP[d][tx + 48];
#pragma unroll
            for (int i = 0; i < 8; i++)
#pragma unroll
                for (int j = 0; j < 4; j++)
                    s[i][j] = fmaf(qf[i], kf[j], s[i][j]);
        }

        const bool diag = (kb == qi);
#pragma unroll
        for (int i = 0; i < 8; i++) {
#pragma unroll
            for (int j = 0; j < 4; j++) {
                float sv = s[i][j] * scale;
                if (diag && (tx + 16 * j) > (ty * 8 + i)) sv = NEG_INF;
                s[i][j] = sv;
            }
        }

#pragma unroll
        for (int i = 0; i < 8; i++) {
            float rm = fmaxf(fmaxf(s[i][0], s[i][1]), fmaxf(s[i][2], s[i][3]));
            rm = fmaxf(rm, __shfl_xor_sync(0xffffffffu, rm, 1));
            rm = fmaxf(rm, __shfl_xor_sync(0xffffffffu, rm, 2));
            rm = fmaxf(rm, __shfl_xor_sync(0xffffffffu, rm, 4));
            rm = fmaxf(rm, __shfl_xor_sync(0xffffffffu, rm, 8));
            const float mn = fmaxf(m[i], rm);
            const float corr = __expf(m[i] - mn);
            m[i] = mn;
            float rs = 0.f;
#pragma unroll
            for (int j = 0; j < 4; j++) {
                const float p = __expf(s[i][j] - mn);
                s[i][j] = p;
                rs += p;
            }
            rs += __shfl_xor_sync(0xffffffffu, rs, 1);
            rs += __shfl_xor_sync(0xffffffffu, rs, 2);
            rs += __shfl_xor_sync(0xffffffffu, rs, 4);
            rs += __shfl_xor_sync(0xffffffffu, rs, 8);
            l[i] = l[i] * corr + rs;
#pragma unroll
            for (int j = 0; j < 4; j++) O[i][j] *= corr;
        }

        __syncthreads();
#pragma unroll
        for (int i = 0; i < 8; i++)
#pragma unroll
            for (int j = 0; j < 4; j++)
                KP[tx + 16 * j][ty * 8 + i] = s[i][j];
        __syncthreads();

#pragma unroll 4
        for (int c = 0; c < 64; c++) {
            float pf[8], vf[4];
            *(float4*)(pf)     = *(const float4*)(&KP[c][ty * 8]);
            *(float4*)(pf + 4) = *(const float4*)(&KP[c][ty * 8 + 4]);
            vf[0] = Vs[c][tx];
            vf[1] = Vs[c][tx + 16];
            vf[2] = Vs[c][tx + 32];
            vf[3] = Vs[c][tx + 48];
#pragma unroll
            for (int i = 0; i < 8; i++)
#pragma unroll
                for (int j = 0; j < 4; j++)
                    O[i][j] = fmaf(pf[i], vf[j], O[i][j]);
        }
    }

    // write O/l into g_y [b][t][h*64+hd], pre-rounded to tf32 for the o-proj
#pragma unroll
    for (int i = 0; i < 8; i++) {
        const float inv = 1.f / l[i];
        const int t = qi * 64 + ty * 8 + i;
        float* dst = g_y + ((size_t)(b * TT + t)) * DD + h * 64;
        dst[tx]      = rtf32(O[i][0] * inv);
        dst[tx + 16] = rtf32(O[i][1] * inv);
        dst[tx + 32] = rtf32(O[i][2] * inv);
        dst[tx + 48] = rtf32(O[i][3] * inv);
    }
}

// ---------------------------------------------------------------------------
extern "C" void kernel_launch(void* const* d_in, const int* in_sizes, int n_in,
                              void* d_out, int out_size)
{
    const float* x     = (const float*)d_in[0];
    const float* w_qkv = (const float*)d_in[1];
    const float* b_qkv = (const float*)d_in[2];
    const float* w_o   = (const float*)d_in[3];
    const float* b_o   = (const float*)d_in[4];
    float* out = (float*)d_out;

    const int smem_bytes = 4 * SBUF * (int)sizeof(float);  // 73728
    cudaFuncSetAttribute(gemm_tf32<0>, cudaFuncAttributeMaxDynamicSharedMemorySize, smem_bytes);
    cudaFuncSetAttribute(gemm_tf32<1>, cudaFuncAttributeMaxDynamicSharedMemorySize, smem_bytes);

    // Prep: round x, transpose+round weights
    round_x_kernel<<<MROWS * DD / (256 * 4), 256>>>(x);
    {
        dim3 g1(3 * DD / 32, DD / 32);  // (96, 32)
        transpose_round_kernel<0><<<g1, 256>>>(w_qkv, DD, 3 * DD);
        dim3 g2(DD / 32, DD / 32);      // (32, 32)
        transpose_round_kernel<1><<<g2, 256>>>(w_o, DD, DD);
    }

    // QKV projection (tensor cores): [4096,1024] @ [1024,3072] -> q/k/v
    {
        dim3 grid(3 * DD / 128, MROWS / 128);  // (24, 32)
        gemm_tf32<0><<<grid, 256, smem_bytes>>>(b_qkv, nullptr, 3 * DD);
    }
    // Flash attention (fp32)
    {
        dim3 grid(TT / 64, BB * HH);           // (32, 32)
        flash_kernel<<<grid, 128>>>();
    }
    // Output projection (tensor cores): [4096,1024] @ [1024,1024] + b_o
    {
        dim3 grid(DD / 128, MROWS / 128);      // (8, 32)
        gemm_tf32<1><<<grid, 256, smem_bytes>>>(b_o, out, DD);
    }
}

// round 9
// speedup vs baseline: 3.5255x; 2.0150x over previous
#include <cuda_runtime.h>
#include <math.h>
#include <stdint.h>

#define BB 2
#define TT 2048
#define DD 1024
#define HH 16
#define HD 64
#define MROWS (BB*TT)   // 4096

// Scratch (allocation-free rule: device globals)
__device__ float g_q[BB*HH*TT*HD];   // [b][h][t][hd]   (tf32-rounded)
__device__ float g_k[BB*HH*TT*HD];   // [b][h][t][hd]   (tf32-rounded)
__device__ float g_v[BB*HH*TT*HD];   // [b][h][hd][t]   TRANSPOSED (tf32-rounded)
__device__ float g_y[BB*TT*DD];      // [b][t][h*64+hd] (tf32-rounded)
__device__ float g_xr[MROWS*DD];     // tf32-rounded x
__device__ float g_wqkvT[3*DD*DD];   // [3D][D] transposed+rounded w_qkv
__device__ float g_woT[DD*DD];       // [D][D] transposed+rounded w_o

#define NEG_INF __int_as_float(0xff800000)

__device__ __forceinline__ float rtf32(float x) {
    uint32_t u;
    asm("cvt.rna.tf32.f32 %0, %1;" : "=r"(u) : "f"(x));
    return __uint_as_float(u);
}

__device__ __forceinline__ unsigned smem_u32(const void* p) {
    return (unsigned)__cvta_generic_to_shared(p);
}

// ---------------------------------------------------------------------------
// Prep kernels
// ---------------------------------------------------------------------------
__global__ __launch_bounds__(256)
void round_x_kernel(const float* __restrict__ x)
{
    int i = (blockIdx.x * 256 + threadIdx.x) * 4;
    float4 v = *(const float4*)(x + i);
    v.x = rtf32(v.x); v.y = rtf32(v.y); v.z = rtf32(v.z); v.w = rtf32(v.w);
    *(float4*)(g_xr + i) = v;
}

template<int WHICH>
__global__ __launch_bounds__(256)
void transpose_round_kernel(const float* __restrict__ src, int R, int C)
{
    float* dst = (WHICH == 0) ? g_wqkvT : g_woT;
    __shared__ float tile[32][33];
    const int r0 = blockIdx.y * 32, c0 = blockIdx.x * 32;
    const int tx = threadIdx.x & 31, ty = threadIdx.x >> 5;
#pragma unroll
    for (int i = 0; i < 32; i += 8)
        tile[ty + i][tx] = src[(size_t)(r0 + ty + i) * C + c0 + tx];
    __syncthreads();
#pragma unroll
    for (int i = 0; i < 32; i += 8)
        dst[(size_t)(c0 + ty + i) * R + r0 + tx] = rtf32(tile[tx][ty + i]);
}

// ---------------------------------------------------------------------------
// TF32 tensor-core GEMM (128x128x32, 8 warps, cp.async double buffer)
// MODE 0: A=g_xr, Bt=g_wqkvT, scatter q/k -> [B,H,T,HD], v -> [B,H,HD,T] (tf32)
// MODE 1: A=g_y,  Bt=g_woT,  plain row-major C (fp32, final output)
// ---------------------------------------------------------------------------
#define SROW 36
#define SBUF (128*SROW)

template<int MODE>
__global__ __launch_bounds__(256, 2)
void gemm_tf32(const float* __restrict__ bias, float* __restrict__ C, int N)
{
    extern __shared__ float sm[];
    float* Asm = sm;
    float* Bsm = sm + 2 * SBUF;
    const int K = DD;

    const int tid  = threadIdx.x;
    const int lane = tid & 31, warp = tid >> 5;
    const int wm = warp >> 2;
    const int wn = warp & 3;
    const int bm = blockIdx.y * 128, bn = blockIdx.x * 128;

    const float* Aeff = (MODE == 0) ? (const float*)g_xr : (const float*)g_y;
    const float* Bt   = (MODE == 0) ? (const float*)g_wqkvT : (const float*)g_woT;

    float acc[4][4][4];
#pragma unroll
    for (int a = 0; a < 4; a++)
#pragma unroll
        for (int b = 0; b < 4; b++)
#pragma unroll
            for (int c = 0; c < 4; c++) acc[a][b][c] = 0.f;

    const int lm = tid >> 3;
    const int lq = (tid & 7) * 4;

    auto copy_chunk = [&](int ck, int buf) {
        const float* ag = Aeff + (size_t)bm * K + ck * 32;
        const float* bg = Bt   + (size_t)bn * K + ck * 32;
        float* as = Asm + buf * SBUF;
        float* bs = Bsm + buf * SBUF;
#pragma unroll
        for (int it = 0; it < 4; it++) {
            const int m = it * 32 + lm;
            unsigned da = smem_u32(as + m * SROW + lq);
            asm volatile("cp.async.cg.shared.global [%0], [%1], 16;\n"
                         :: "r"(da), "l"(ag + (size_t)m * K + lq) : "memory");
            unsigned db = smem_u32(bs + m * SROW + lq);
            asm volatile("cp.async.cg.shared.global [%0], [%1], 16;\n"
                         :: "r"(db), "l"(bg + (size_t)m * K + lq) : "memory");
        }
        asm volatile("cp.async.commit_group;\n" ::: "memory");
    };

    copy_chunk(0, 0);

    const int j8  = lane & 7;
    const int sub = lane >> 3;

    for (int ck = 0; ck < 32; ck++) {
        asm volatile("cp.async.wait_group 0;\n" ::: "memory");
        __syncthreads();
        if (ck + 1 < 32) copy_chunk(ck + 1, (ck + 1) & 1);

        const float* as = Asm + (ck & 1) * SBUF;
        const float* bs = Bsm + (ck & 1) * SBUF;

#pragma unroll
        for (int ks = 0; ks < 4; ks++) {
            const int k8 = ks * 8;
            uint32_t a[4][4];
#pragma unroll
            for (int mf = 0; mf < 4; mf++) {
                const int row = wm * 64 + mf * 16 + (sub & 1) * 8 + j8;
                const int col = k8 + (sub >> 1) * 4;
                unsigned addr = smem_u32(as + row * SROW + col);
                asm volatile("ldmatrix.sync.aligned.m8n8.x4.shared.b16 {%0,%1,%2,%3}, [%4];\n"
                             : "=r"(a[mf][0]), "=r"(a[mf][1]), "=r"(a[mf][2]), "=r"(a[mf][3])
                             : "r"(addr));
            }
            uint32_t b[4][2];
#pragma unroll
            for (int np = 0; np < 2; np++) {
                const int row = wn * 32 + np * 16 + (sub >> 1) * 8 + j8;
                const int col = k8 + (sub & 1) * 4;
                unsigned addr = smem_u32(bs + row * SROW + col);
                asm volatile("ldmatrix.sync.aligned.m8n8.x4.shared.b16 {%0,%1,%2,%3}, [%4];\n"
                             : "=r"(b[2*np][0]), "=r"(b[2*np][1]),
                               "=r"(b[2*np+1][0]), "=r"(b[2*np+1][1])
                             : "r"(addr));
            }
#pragma unroll
            for (int mf = 0; mf < 4; mf++)
#pragma unroll
                for (int nf = 0; nf < 4; nf++)
                    asm volatile(
                        "mma.sync.aligned.m16n8k8.row.col.f32.tf32.tf32.f32 "
                        "{%0,%1,%2,%3}, {%4,%5,%6,%7}, {%8,%9}, {%0,%1,%2,%3};\n"
                        : "+f"(acc[mf][nf][0]), "+f"(acc[mf][nf][1]),
                          "+f"(acc[mf][nf][2]), "+f"(acc[mf][nf][3])
                        : "r"(a[mf][0]), "r"(a[mf][1]), "r"(a[mf][2]), "r"(a[mf][3]),
                          "r"(b[nf][0]), "r"(b[nf][1]));
        }
    }

    // Epilogue
    const int g  = lane >> 2;
    const int tg = lane & 3;
#pragma unroll
    for (int mf = 0; mf < 4; mf++) {
#pragma unroll
        for (int nf = 0; nf < 4; nf++) {
            const int col  = bn + wn * 32 + nf * 8 + 2 * tg;
            const float b0 = bias[col], b1 = bias[col + 1];
            const int row0 = bm + wm * 64 + mf * 16 + g;
            float v00 = acc[mf][nf][0] + b0, v01 = acc[mf][nf][1] + b1;
            float v10 = acc[mf][nf][2] + b0, v11 = acc[mf][nf][3] + b1;
            if (MODE == 0) {
                v00 = rtf32(v00); v01 = rtf32(v01);
                v10 = rtf32(v10); v11 = rtf32(v11);
                const int part = col >> 10;
                const int rem  = col & 1023;
                const int h    = rem >> 6;
                const int hd0  = rem & 63;
#pragma unroll
                for (int rr = 0; rr < 2; rr++) {
                    const int row = row0 + rr * 8;
                    const int bb = row >> 11;
                    const int t  = row & (TT - 1);
                    const float vx = rr ? v10 : v00;
                    const float vy = rr ? v11 : v01;
                    if (part == 2) {
                        // V transposed: [b][h][hd][t]
                        float* dst = g_v + ((size_t)((bb * HH + h) * HD + hd0)) * TT + t;
                        dst[0]  = vx;
                        dst[TT] = vy;
                    } else {
                        float* dbase = (part == 0) ? g_q : g_k;
                        *(float2*)(dbase + ((size_t)((bb * HH + h) * TT + t)) * HD + hd0)
                            = make_float2(vx, vy);
                    }
                }
            } else {
                *(float2*)(C + (size_t)row0 * N + col)       = make_float2(v00, v01);
                *(float2*)(C + (size_t)(row0 + 8) * N + col) = make_float2(v10, v11);
            }
        }
    }
}

// ---------------------------------------------------------------------------
// Tensor-core flash attention.
// Block: 128 threads (4 warps), 128 q-rows per block, KV tiles of 64.
// Grid: (T/128=16, B*H=32). Warp w owns q rows w*32..w*32+31.
// S mma: A=Q [q][d], B=K [kv][d]. PV mma: A=P [q][kv], B=Vt [d][kv] (g_v layout).
// ---------------------------------------------------------------------------
#define QT 128
#define FSTR 68

__global__ __launch_bounds__(128, 2)
void flash_tc()
{
    extern __shared__ float fsm[];
    float* Qs = fsm;                  // [128][FSTR]
    float* Ks = Qs + QT * FSTR;       // [64][FSTR]
    float* Vt = Ks + 64 * FSTR;       // [64][FSTR]  Vt[d][c]
    float* Ps = Vt + 64 * FSTR;       // [128][FSTR]

    const int tid  = threadIdx.x;
    const int lane = tid & 31, warp = tid >> 5;
    const int j8 = lane & 7, sub = lane >> 3;
    const int g  = lane >> 2, tg  = lane & 3;
    const int qi = blockIdx.x;        // 0..15
    const int bh = blockIdx.y;        // 0..31
    const int b = bh >> 4, h = bh & 15;

    const float* qg = g_q + ((size_t)bh * TT + qi * QT) * HD;
    const float* kg = g_k + (size_t)bh * TT * HD;
    const float* vg = g_v + (size_t)bh * HD * TT;   // [d][t]

    // Load Q tile, fold in scale 1/32 (power of two: tf32-exact)
#pragma unroll
    for (int it = 0; it < 16; it++) {
        const int u = it * 128 + tid;
        const int r = u >> 4, c4 = (u & 15) << 2;
        float4 v = *(const float4*)(qg + (size_t)r * HD + c4);
        float* dst = Qs + r * FSTR + c4;
        dst[0] = v.x * 0.03125f; dst[1] = v.y * 0.03125f;
        dst[2] = v.z * 0.03125f; dst[3] = v.w * 0.03125f;
    }

    float O[2][8][4];
    float m[2][2], l[2][2];
#pragma unroll
    for (int mf = 0; mf < 2; mf++) {
        m[mf][0] = NEG_INF; m[mf][1] = NEG_INF;
        l[mf][0] = 0.f;     l[mf][1] = 0.f;
#pragma unroll
        for (int nf = 0; nf < 8; nf++)
#pragma unroll
            for (int e = 0; e < 4; e++) O[mf][nf][e] = 0.f;
    }

    const int nkv = 2 * qi + 2;
    for (int kb = 0; kb < nkv; kb++) {
        __syncthreads();   // prior iter's PV reads of Vt done; Q visible (iter 0)
        // Load K tile [kv][d] and Vt tile [d][t-slice] (both natural row-major)
#pragma unroll
        for (int it = 0; it < 8; it++) {
            const int u = it * 128 + tid;
            const int r = u >> 4, c4 = (u & 15) << 2;
            *(float4*)(Ks + r * FSTR + c4) =
                *(const float4*)(kg + (size_t)(kb * 64 + r) * HD + c4);
            *(float4*)(Vt + r * FSTR + c4) =
                *(const float4*)(vg + (size_t)r * TT + kb * 64 + c4);
        }
        __syncthreads();

        // ---- S = (Q*scale) @ K^T ----
        float acc[2][8][4];
#pragma unroll
        for (int mf = 0; mf < 2; mf++)
#pragma unroll
            for (int nf = 0; nf < 8; nf++)
#pragma unroll
                for (int e = 0; e < 4; e++) acc[mf][nf][e] = 0.f;

#pragma unroll
        for (int ks = 0; ks < 8; ks++) {
            const int k8 = ks * 8;
            uint32_t a[2][4];
#pragma unroll
            for (int mf = 0; mf < 2; mf++) {
                const int row = warp * 32 + mf * 16 + (sub & 1) * 8 + j8;
                unsigned addr = smem_u32(Qs + row * FSTR + k8 + (sub >> 1) * 4);
                asm volatile("ldmatrix.sync.aligned.m8n8.x4.shared.b16 {%0,%1,%2,%3}, [%4];\n"
                             : "=r"(a[mf][0]), "=r"(a[mf][1]), "=r"(a[mf][2]), "=r"(a[mf][3])
                             : "r"(addr));
            }
            uint32_t bf[8][2];
#pragma unroll
            for (int np = 0; np < 4; np++) {
                const int row = np * 16 + (sub >> 1) * 8 + j8;
                unsigned addr = smem_u32(Ks + row * FSTR + k8 + (sub & 1) * 4);
                asm volatile("ldmatrix.sync.aligned.m8n8.x4.shared.b16 {%0,%1,%2,%3}, [%4];\n"
                             : "=r"(bf[2*np][0]), "=r"(bf[2*np][1]),
                               "=r"(bf[2*np+1][0]), "=r"(bf[2*np+1][1])
                             : "r"(addr));
            }
#pragma unroll
            for (int mf = 0; mf < 2; mf++)
#pragma unroll
                for (int nf = 0; nf < 8; nf++)
                    asm volatile(
                        "mma.sync.aligned.m16n8k8.row.col.f32.tf32.tf32.f32 "
                        "{%0,%1,%2,%3}, {%4,%5,%6,%7}, {%8,%9}, {%0,%1,%2,%3};\n"
                        : "+f"(acc[mf][nf][0]), "+f"(acc[mf][nf][1]),
                          "+f"(acc[mf][nf][2]), "+f"(acc[mf][nf][3])
                        : "r"(a[mf][0]), "r"(a[mf][1]), "r"(a[mf][2]), "r"(a[mf][3]),
                          "r"(bf[nf][0]), "r"(bf[nf][1]));
        }

        // ---- causal mask (only last two kv tiles can intersect diagonal) ----
        if (kb >= 2 * qi) {
            const int col0 = kb * 64 + 2 * tg;
            const int row0 = qi * QT + warp * 32 + g;
#pragma unroll
            for (int mf = 0; mf < 2; mf++)
#pragma unroll
                for (int nf = 0; nf < 8; nf++)
#pragma unroll
                    for (int e = 0; e < 4; e++) {
                        const int row = row0 + mf * 16 + (e >> 1) * 8;
                        const int col = col0 + nf * 8 + (e & 1);
                        if (col > row) acc[mf][nf][e] = NEG_INF;
                    }
        }

        // ---- online softmax on fragments ----
#pragma unroll
        for (int mf = 0; mf < 2; mf++)
#pragma unroll
            for (int rr = 0; rr < 2; rr++) {
                float rm = NEG_INF;
#pragma unroll
                for (int nf = 0; nf < 8; nf++)
                    rm = fmaxf(rm, fmaxf(acc[mf][nf][rr*2], acc[mf][nf][rr*2+1]));
                rm = fmaxf(rm, __shfl_xor_sync(0xffffffffu, rm, 1));
                rm = fmaxf(rm, __shfl_xor_sync(0xffffffffu, rm, 2));
                const float mo = m[mf][rr];
                const float mn = fmaxf(mo, rm);
                const float corr = __expf(mo - mn);
                m[mf][rr] = mn;
                float rs = 0.f;
#pragma unroll
                for (int nf = 0; nf < 8; nf++) {
                    const float p0 = __expf(acc[mf][nf][rr*2]   - mn);
                    const float p1 = __expf(acc[mf][nf][rr*2+1] - mn);
                    acc[mf][nf][rr*2]   = p0;
                    acc[mf][nf][rr*2+1] = p1;
                    rs += p0 + p1;
                }
                rs += __shfl_xor_sync(0xffffffffu, rs, 1);
                rs += __shfl_xor_sync(0xffffffffu, rs, 2);
                l[mf][rr] = l[mf][rr] * corr + rs;
#pragma unroll
                for (int nf = 0; nf < 8; nf++) {
                    O[mf][nf][rr*2]   *= corr;
                    O[mf][nf][rr*2+1] *= corr;
                }
            }

        // ---- write P to smem (own-warp rows only), tf32-rounded ----
#pragma unroll
        for (int mf = 0; mf < 2; mf++) {
            const int r0 = warp * 32 + mf * 16 + g;
#pragma unroll
            for (int nf = 0; nf < 8; nf++) {
                const int col = nf * 8 + 2 * tg;
                *(float2*)(Ps + r0 * FSTR + col) =
                    make_float2(rtf32(acc[mf][nf][0]), rtf32(acc[mf][nf][1]));
                *(float2*)(Ps + (r0 + 8) * FSTR + col) =
                    make_float2(rtf32(acc[mf][nf][2]), rtf32(acc[mf][nf][3]));
            }
        }
        __syncwarp();

        // ---- O += P @ V  (A = Ps [q][c], B = Vt [d][c]) ----
#pragma unroll
        for (int ks = 0; ks < 8; ks++) {
            const int k8 = ks * 8;
            uint32_t a[2][4];
#pragma unroll
            for (int mf = 0; mf < 2; mf++) {
                const int row = warp * 32 + mf * 16 + (sub & 1) * 8 + j8;
                unsigned addr = smem_u32(Ps + row * FSTR + k8 + (sub >> 1) * 4);
                asm volatile("ldmatrix.sync.aligned.m8n8.x4.shared.b16 {%0,%1,%2,%3}, [%4];\n"
                             : "=r"(a[mf][0]), "=r"(a[mf][1]), "=r"(a[mf][2]), "=r"(a[mf][3])
                             : "r"(addr));
            }
            uint32_t bf[8][2];
#pragma unroll
            for (int np = 0; np < 4; np++) {
                const int row = np * 16 + (sub >> 1) * 8 + j8;
                unsigned addr = smem_u32(Vt + row * FSTR + k8 + (sub & 1) * 4);
                asm volatile("ldmatrix.sync.aligned.m8n8.x4.shared.b16 {%0,%1,%2,%3}, [%4];\n"
                             : "=r"(bf[2*np][0]), "=r"(bf[2*np][1]),
                               "=r"(bf[2*np+1][0]), "=r"(bf[2*np+1][1])
                             : "r"(addr));
            }
#pragma unroll
            for (int mf = 0; mf < 2; mf++)
#pragma unroll
                for (int nf = 0; nf < 8; nf++)
                    asm volatile(
                        "mma.sync.aligned.m16n8k8.row.col.f32.tf32.tf32.f32 "
                        "{%0,%1,%2,%3}, {%4,%5,%6,%7}, {%8,%9}, {%0,%1,%2,%3};\n"
                        : "+f"(O[mf][nf][0]), "+f"(O[mf][nf][1]),
                          "+f"(O[mf][nf][2]), "+f"(O[mf][nf][3])
                        : "r"(a[mf][0]), "r"(a[mf][1]), "r"(a[mf][2]), "r"(a[mf][3]),
                          "r"(bf[nf][0]), "r"(bf[nf][1]));
        }
    }

    // ---- epilogue: normalize, tf32-round, write g_y [b][t][h*64+d] ----
#pragma unroll
    for (int mf = 0; mf < 2; mf++)
#pragma unroll
        for (int rr = 0; rr < 2; rr++) {
            const float inv = 1.f / l[mf][rr];
            const int t = qi * QT + warp * 32 + mf * 16 + g + rr * 8;
            float* dst = g_y + ((size_t)(b * TT + t)) * DD + h * 64;
#pragma unroll
            for (int nf = 0; nf < 8; nf++) {
                const int d0 = nf * 8 + 2 * tg;
                *(float2*)(dst + d0) =
                    make_float2(rtf32(O[mf][nf][rr*2] * inv),
                                rtf32(O[mf][nf][rr*2+1] * inv));
            }
        }
}

// ---------------------------------------------------------------------------
extern "C" void kernel_launch(void* const* d_in, const int* in_sizes, int n_in,
                              void* d_out, int out_size)
{
    const float* x     = (const float*)d_in[0];
    const float* w_qkv = (const float*)d_in[1];
    const float* b_qkv = (const float*)d_in[2];
    const float* w_o   = (const float*)d_in[3];
    const float* b_o   = (const float*)d_in[4];
    float* out = (float*)d_out;

    const int gemm_smem  = 4 * SBUF * (int)sizeof(float);              // 73728
    const int flash_smem = (QT + 64 + 64 + QT) * FSTR * (int)sizeof(float);  // 104448
    cudaFuncSetAttribute(gemm_tf32<0>, cudaFuncAttributeMaxDynamicSharedMemorySize, gemm_smem);
    cudaFuncSetAttribute(gemm_tf32<1>, cudaFuncAttributeMaxDynamicSharedMemorySize, gemm_smem);
    cudaFuncSetAttribute(flash_tc,     cudaFuncAttributeMaxDynamicSharedMemorySize, flash_smem);

    // Prep
    round_x_kernel<<<MROWS * DD / (256 * 4), 256>>>(x);
    {
        dim3 g1(3 * DD / 32, DD / 32);
        transpose_round_kernel<0><<<g1, 256>>>(w_qkv, DD, 3 * DD);
        dim3 g2(DD / 32, DD / 32);
        transpose_round_kernel<1><<<g2, 256>>>(w_o, DD, DD);
    }

    // QKV projection (tensor cores)
    {
        dim3 grid(3 * DD / 128, MROWS / 128);
        gemm_tf32<0><<<grid, 256, gemm_smem>>>(b_qkv, nullptr, 3 * DD);
    }
    // Flash attention (tensor cores)
    {
        dim3 grid(TT / QT, BB * HH);   // (16, 32)
        flash_tc<<<grid, 128, flash_smem>>>();
    }
    // Output projection (tensor cores)
    {
        dim3 grid(DD / 128, MROWS / 128);
        gemm_tf32<1><<<grid, 256, gemm_smem>>>(b_o, out, DD);
    }
}

// round 11
// speedup vs baseline: 3.6323x; 1.0303x over previous
#include <cuda_runtime.h>
#include <math.h>
#include <stdint.h>

#define BB 2
#define TT 2048
#define DD 1024
#define HH 16
#define HD 64
#define MROWS (BB*TT)   // 4096

// Scratch (allocation-free rule: device globals)
__device__ float g_q[BB*HH*TT*HD];   // [b][h][t][hd]   (tf32-rounded)
__device__ float g_k[BB*HH*TT*HD];   // [b][h][t][hd]   (tf32-rounded)
__device__ float g_v[BB*HH*TT*HD];   // [b][h][hd][t]   TRANSPOSED (tf32-rounded)
__device__ float g_y[BB*TT*DD];      // [b][t][h*64+hd] (tf32-rounded)
__device__ float g_xr[MROWS*DD];     // tf32-rounded x
__device__ float g_wqkvT[3*DD*DD];   // [3D][D] transposed+rounded w_qkv
__device__ float g_woT[DD*DD];       // [D][D] transposed+rounded w_o

#define NEG_INF __int_as_float(0xff800000)

__device__ __forceinline__ float rtf32(float x) {
    uint32_t u;
    asm("cvt.rna.tf32.f32 %0, %1;" : "=r"(u) : "f"(x));
    return __uint_as_float(u);
}

__device__ __forceinline__ unsigned smem_u32(const void* p) {
    return (unsigned)__cvta_generic_to_shared(p);
}

// ---------------------------------------------------------------------------
// Prep kernels
// ---------------------------------------------------------------------------
__global__ __launch_bounds__(256)
void round_x_kernel(const float* __restrict__ x)
{
    int i = (blockIdx.x * 256 + threadIdx.x) * 4;
    float4 v = *(const float4*)(x + i);
    v.x = rtf32(v.x); v.y = rtf32(v.y); v.z = rtf32(v.z); v.w = rtf32(v.w);
    *(float4*)(g_xr + i) = v;
}

template<int WHICH>
__global__ __launch_bounds__(256)
void transpose_round_kernel(const float* __restrict__ src, int R, int C)
{
    float* dst = (WHICH == 0) ? g_wqkvT : g_woT;
    __shared__ float tile[32][33];
    const int r0 = blockIdx.y * 32, c0 = blockIdx.x * 32;
    const int tx = threadIdx.x & 31, ty = threadIdx.x >> 5;
#pragma unroll
    for (int i = 0; i < 32; i += 8)
        tile[ty + i][tx] = src[(size_t)(r0 + ty + i) * C + c0 + tx];
    __syncthreads();
#pragma unroll
    for (int i = 0; i < 32; i += 8)
        dst[(size_t)(c0 + ty + i) * R + r0 + tx] = rtf32(tile[tx][ty + i]);
}

// ---------------------------------------------------------------------------
// TF32 tensor-core GEMM (128x128x32, 8 warps, cp.async 3-stage pipeline)
// MODE 0: A=g_xr, Bt=g_wqkvT, scatter q/k -> [B,H,T,HD], v -> [B,H,HD,T] (tf32)
// MODE 1: A=g_y,  Bt=g_woT,  plain row-major C (fp32, final output)
// ---------------------------------------------------------------------------
#define SROW 36
#define SBUF (128*SROW)

template<int MODE>
__global__ __launch_bounds__(256, 2)
void gemm_tf32(const float* __restrict__ bias, float* __restrict__ C, int N)
{
    extern __shared__ float sm[];
    float* Asm = sm;              // 3 buffers
    float* Bsm = sm + 3 * SBUF;   // 3 buffers
    const int K = DD;

    const int tid  = threadIdx.x;
    const int lane = tid & 31, warp = tid >> 5;
    const int wm = warp >> 2;
    const int wn = warp & 3;
    const int bm = blockIdx.y * 128, bn = blockIdx.x * 128;

    const float* Aeff = (MODE == 0) ? (const float*)g_xr : (const float*)g_y;
    const float* Bt   = (MODE == 0) ? (const float*)g_wqkvT : (const float*)g_woT;

    float acc[4][4][4];
#pragma unroll
    for (int a = 0; a < 4; a++)
#pragma unroll
        for (int b = 0; b < 4; b++)
#pragma unroll
            for (int c = 0; c < 4; c++) acc[a][b][c] = 0.f;

    const int lm = tid >> 3;
    const int lq = (tid & 7) * 4;

    auto copy_chunk = [&](int ck, int buf) {
        const float* ag = Aeff + (size_t)bm * K + ck * 32;
        const float* bg = Bt   + (size_t)bn * K + ck * 32;
        float* as = Asm + buf * SBUF;
        float* bs = Bsm + buf * SBUF;
#pragma unroll
        for (int it = 0; it < 4; it++) {
            const int m = it * 32 + lm;
            unsigned da = smem_u32(as + m * SROW + lq);
            asm volatile("cp.async.cg.shared.global [%0], [%1], 16;\n"
                         :: "r"(da), "l"(ag + (size_t)m * K + lq) : "memory");
            unsigned db = smem_u32(bs + m * SROW + lq);
            asm volatile("cp.async.cg.shared.global [%0], [%1], 16;\n"
                         :: "r"(db), "l"(bg + (size_t)m * K + lq) : "memory");
        }
        asm volatile("cp.async.commit_group;\n" ::: "memory");
    };

    copy_chunk(0, 0);
    copy_chunk(1, 1);

    const int j8  = lane & 7;
    const int sub = lane >> 3;

    int cur = 0;
    for (int ck = 0; ck < 32; ck++) {
        if (ck < 31) { asm volatile("cp.async.wait_group 1;\n" ::: "memory"); }
        else         { asm volatile("cp.async.wait_group 0;\n" ::: "memory"); }
        __syncthreads();
        if (ck + 2 < 32) {
            int pf = cur + 2; if (pf >= 3) pf -= 3;
            copy_chunk(ck + 2, pf);
        }

        const float* as = Asm + cur * SBUF;
        const float* bs = Bsm + cur * SBUF;

#pragma unroll
        for (int ks = 0; ks < 4; ks++) {
            const int k8 = ks * 8;
            uint32_t a[4][4];
#pragma unroll
            for (int mf = 0; mf < 4; mf++) {
                const int row = wm * 64 + mf * 16 + (sub & 1) * 8 + j8;
                const int col = k8 + (sub >> 1) * 4;
                unsigned addr = smem_u32(as + row * SROW + col);
                asm volatile("ldmatrix.sync.aligned.m8n8.x4.shared.b16 {%0,%1,%2,%3}, [%4];\n"
                             : "=r"(a[mf][0]), "=r"(a[mf][1]), "=r"(a[mf][2]), "=r"(a[mf][3])
                             : "r"(addr));
            }
            uint32_t b[4][2];
#pragma unroll
            for (int np = 0; np < 2; np++) {
                const int row = wn * 32 + np * 16 + (sub >> 1) * 8 + j8;
                const int col = k8 + (sub & 1) * 4;
                unsigned addr = smem_u32(bs + row * SROW + col);
                asm volatile("ldmatrix.sync.aligned.m8n8.x4.shared.b16 {%0,%1,%2,%3}, [%4];\n"
                             : "=r"(b[2*np][0]), "=r"(b[2*np][1]),
                               "=r"(b[2*np+1][0]), "=r"(b[2*np+1][1])
                             : "r"(addr));
            }
#pragma unroll
            for (int mf = 0; mf < 4; mf++)
#pragma unroll
                for (int nf = 0; nf < 4; nf++)
                    asm volatile(
                        "mma.sync.aligned.m16n8k8.row.col.f32.tf32.tf32.f32 "
                        "{%0,%1,%2,%3}, {%4,%5,%6,%7}, {%8,%9}, {%0,%1,%2,%3};\n"
                        : "+f"(acc[mf][nf][0]), "+f"(acc[mf][nf][1]),
                          "+f"(acc[mf][nf][2]), "+f"(acc[mf][nf][3])
                        : "r"(a[mf][0]), "r"(a[mf][1]), "r"(a[mf][2]), "r"(a[mf][3]),
                          "r"(b[nf][0]), "r"(b[nf][1]));
        }
        cur = (cur + 1 == 3) ? 0 : cur + 1;
    }

    // Epilogue
    const int g  = lane >> 2;
    const int tg = lane & 3;
#pragma unroll
    for (int mf = 0; mf < 4; mf++) {
#pragma unroll
        for (int nf = 0; nf < 4; nf++) {
            const int col  = bn + wn * 32 + nf * 8 + 2 * tg;
            const float b0 = bias[col], b1 = bias[col + 1];
            const int row0 = bm + wm * 64 + mf * 16 + g;
            float v00 = acc[mf][nf][0] + b0, v01 = acc[mf][nf][1] + b1;
            float v10 = acc[mf][nf][2] + b0, v11 = acc[mf][nf][3] + b1;
            if (MODE == 0) {
                v00 = rtf32(v00); v01 = rtf32(v01);
                v10 = rtf32(v10); v11 = rtf32(v11);
                const int part = col >> 10;
                const int rem  = col & 1023;
                const int h    = rem >> 6;
                const int hd0  = rem & 63;
#pragma unroll
                for (int rr = 0; rr < 2; rr++) {
                    const int row = row0 + rr * 8;
                    const int bb = row >> 11;
                    const int t  = row & (TT - 1);
                    const float vx = rr ? v10 : v00;
                    const float vy = rr ? v11 : v01;
                    if (part == 2) {
                        // V transposed: [b][h][hd][t]
                        float* dst = g_v + ((size_t)((bb * HH + h) * HD + hd0)) * TT + t;
                        dst[0]  = vx;
                        dst[TT] = vy;
                    } else {
                        float* dbase = (part == 0) ? g_q : g_k;
                        *(float2*)(dbase + ((size_t)((bb * HH + h) * TT + t)) * HD + hd0)
                            = make_float2(vx, vy);
                    }
                }
            } else {
                *(float2*)(C + (size_t)row0 * N + col)       = make_float2(v00, v01);
                *(float2*)(C + (size_t)(row0 + 8) * N + col) = make_float2(v10, v11);
            }
        }
    }
}

// ---------------------------------------------------------------------------
// Tensor-core flash attention, v2.
// Block: 256 threads (8 warps), 128 q-rows per block (16 per warp), KV tiles 64.
// Q held in registers as A-fragments (staged once through the P buffer).
// K/V double-buffered via cp.async. Softmax in exp2 domain (log2e folded in Q).
// Grid: (T/128=16, B*H=32).
// ---------------------------------------------------------------------------
#define QT 128
#define FSTR 68

__global__ __launch_bounds__(256, 2)
void flash_tc()
{
    extern __shared__ float fsm[];
    float* Ps  = fsm;                  // [128][FSTR]  (Q staging, then P)
    float* Ksm = fsm + QT * FSTR;      // 2 x [64][FSTR]
    float* Vsm = Ksm + 2 * 64 * FSTR;  // 2 x [64][FSTR]  Vt[d][c]

    const int tid  = threadIdx.x;
    const int lane = tid & 31, warp = tid >> 5;       // warp 0..7
    const int j8 = lane & 7, sub = lane >> 3;
    const int g  = lane >> 2, tg  = lane & 3;
    const int qi = blockIdx.x;        // 0..15
    const int bh = blockIdx.y;        // 0..31
    const int b = bh >> 4, h = bh & 15;

    const float* qg = g_q + ((size_t)bh * TT + qi * QT) * HD;
    const float* kg = g_k + (size_t)bh * TT * HD;
    const float* vg = g_v + (size_t)bh * HD * TT;     // [d][t]

    // Stage Q into Ps with scale = log2(e)/32 folded in, rna-tf32 rounded.
    const float qscale = 1.44269504088896340736f * 0.03125f;
#pragma unroll
    for (int it = 0; it < 8; it++) {
        const int u = it * 256 + tid;
        const int r = u >> 4, c4 = (u & 15) << 2;
        float4 v = *(const float4*)(qg + (size_t)r * HD + c4);
        float* dst = Ps + r * FSTR + c4;
        dst[0] = rtf32(v.x * qscale); dst[1] = rtf32(v.y * qscale);
        dst[2] = rtf32(v.z * qscale); dst[3] = rtf32(v.w * qscale);
    }

    auto copy_kv = [&](int kb, int buf) {
        float* kd = Ksm + buf * (64 * FSTR);
        float* vd = Vsm + buf * (64 * FSTR);
#pragma unroll
        for (int it = 0; it < 4; it++) {
            const int u = it * 256 + tid;
            const int r = u >> 4, c4 = (u & 15) << 2;
            asm volatile("cp.async.cg.shared.global [%0], [%1], 16;\n"
                         :: "r"(smem_u32(kd + r * FSTR + c4)),
                            "l"(kg + (size_t)(kb * 64 + r) * HD + c4) : "memory");
            asm volatile("cp.async.cg.shared.global [%0], [%1], 16;\n"
                         :: "r"(smem_u32(vd + r * FSTR + c4)),
                            "l"(vg + (size_t)r * TT + kb * 64 + c4) : "memory");
        }
        asm volatile("cp.async.commit_group;\n" ::: "memory");
    };

    copy_kv(0, 0);
    asm volatile("cp.async.wait_group 0;\n" ::: "memory");
    __syncthreads();   // kv tile 0 + Q staging visible

    // Load Q A-fragments into registers (own-warp rows only), then Ps is free.
    uint32_t aq[8][4];
#pragma unroll
    for (int ks = 0; ks < 8; ks++) {
        const int row = warp * 16 + (sub & 1) * 8 + j8;
        unsigned addr = smem_u32(Ps + row * FSTR + ks * 8 + (sub >> 1) * 4);
        asm volatile("ldmatrix.sync.aligned.m8n8.x4.shared.b16 {%0,%1,%2,%3}, [%4];\n"
                     : "=r"(aq[ks][0]), "=r"(aq[ks][1]), "=r"(aq[ks][2]), "=r"(aq[ks][3])
                     : "r"(addr));
    }

    float O[8][4];
    float m[2] = {NEG_INF, NEG_INF}, l[2] = {0.f, 0.f};
#pragma unroll
    for (int nf = 0; nf < 8; nf++)
#pragma unroll
        for (int e = 0; e < 4; e++) O[nf][e] = 0.f;

    const int nkv = 2 * qi + 2;
    for (int kb = 0; kb < nkv; kb++) {
        const int cur = kb & 1;
        if (kb + 1 < nkv) {
            copy_kv(kb + 1, cur ^ 1);
            asm volatile("cp.async.wait_group 1;\n" ::: "memory");
        } else {
            asm volatile("cp.async.wait_group 0;\n" ::: "memory");
        }
        __syncthreads();   // tile kb visible to all warps

        // Skip tiles fully above the diagonal for this warp's rows.
        const bool active = (kb * 64 <= qi * QT + warp * 16 + 15);
        if (active) {
            const float* Kc = Ksm + cur * (64 * FSTR);
            const float* Vc = Vsm + cur * (64 * FSTR);

            // ---- S = (Q*scale*log2e) @ K^T ----
            float acc[8][4];
#pragma unroll
            for (int nf = 0; nf < 8; nf++)
#pragma unroll
                for (int e = 0; e < 4; e++) acc[nf][e] = 0.f;

#pragma unroll
            for (int ks = 0; ks < 8; ks++) {
                const int k8 = ks * 8;
                uint32_t bf[8][2];
#pragma unroll
                for (int np = 0; np < 4; np++) {
                    const int row = np * 16 + (sub >> 1) * 8 + j8;
                    unsigned addr = smem_u32(Kc + row * FSTR + k8 + (sub & 1) * 4);
                    asm volatile("ldmatrix.sync.aligned.m8n8.x4.shared.b16 {%0,%1,%2,%3}, [%4];\n"
                                 : "=r"(bf[2*np][0]), "=r"(bf[2*np][1]),
                                   "=r"(bf[2*np+1][0]), "=r"(bf[2*np+1][1])
                                 : "r"(addr));
                }
#pragma unroll
                for (int nf = 0; nf < 8; nf++)
                    asm volatile(
                        "mma.sync.aligned.m16n8k8.row.col.f32.tf32.tf32.f32 "
                        "{%0,%1,%2,%3}, {%4,%5,%6,%7}, {%8,%9}, {%0,%1,%2,%3};\n"
                        : "+f"(acc[nf][0]), "+f"(acc[nf][1]),
                          "+f"(acc[nf][2]), "+f"(acc[nf][3])
                        : "r"(aq[ks][0]), "r"(aq[ks][1]), "r"(aq[ks][2]), "r"(aq[ks][3]),
                          "r"(bf[nf][0]), "r"(bf[nf][1]));
            }

            // ---- causal mask ----
            if (kb >= 2 * qi) {
                const int col0 = kb * 64 + 2 * tg;
                const int row0 = qi * QT + warp * 16 + g;
#pragma unroll
                for (int nf = 0; nf < 8; nf++)
#pragma unroll
                    for (int e = 0; e < 4; e++) {
                        const int row = row0 + (e >> 1) * 8;
                        const int col = col0 + nf * 8 + (e & 1);
                        if (col > row) acc[nf][e] = NEG_INF;
                    }
            }

            // ---- online softmax (exp2 domain) ----
#pragma unroll
            for (int rr = 0; rr < 2; rr++) {
                float rm = NEG_INF;
#pragma unroll
                for (int nf = 0; nf < 8; nf++)
                    rm = fmaxf(rm, fmaxf(acc[nf][rr*2], acc[nf][rr*2+1]));
                rm = fmaxf(rm, __shfl_xor_sync(0xffffffffu, rm, 1));
                rm = fmaxf(rm, __shfl_xor_sync(0xffffffffu, rm, 2));
                const float mo = m[rr];
                const float mn = fmaxf(mo, rm);
                const float corr = exp2f(mo - mn);
                m[rr] = mn;
                float rs = 0.f;
#pragma unroll
                for (int nf = 0; nf < 8; nf++) {
                    const float p0 = exp2f(acc[nf][rr*2]   - mn);
                    const float p1 = exp2f(acc[nf][rr*2+1] - mn);
                    acc[nf][rr*2]   = p0;
                    acc[nf][rr*2+1] = p1;
                    rs += p0 + p1;
                }
                rs += __shfl_xor_sync(0xffffffffu, rs, 1);
                rs += __shfl_xor_sync(0xffffffffu, rs, 2);
                l[rr] = l[rr] * corr + rs;
#pragma unroll
                for (int nf = 0; nf < 8; nf++) {
                    O[nf][rr*2]   *= corr;
                    O[nf][rr*2+1] *= corr;
                }
            }

            // ---- write P (own-warp rows), tf32-rounded ----
            {
                const int r0 = warp * 16 + g;
#pragma unroll
                for (int nf = 0; nf < 8; nf++) {
                    const int col = nf * 8 + 2 * tg;
                    *(float2*)(Ps + r0 * FSTR + col) =
                        make_float2(rtf32(acc[nf][0]), rtf32(acc[nf][1]));
                    *(float2*)(Ps + (r0 + 8) * FSTR + col) =
                        make_float2(rtf32(acc[nf][2]), rtf32(acc[nf][3]));
                }
            }
            __syncwarp();

            // ---- O += P @ V ----
#pragma unroll
            for (int ks = 0; ks < 8; ks++) {
                const int k8 = ks * 8;
                uint32_t a[4];
                {
                    const int row = warp * 16 + (sub & 1) * 8 + j8;
                    unsigned addr = smem_u32(Ps + row * FSTR + k8 + (sub >> 1) * 4);
                    asm volatile("ldmatrix.sync.aligned.m8n8.x4.shared.b16 {%0,%1,%2,%3}, [%4];\n"
                                 : "=r"(a[0]), "=r"(a[1]), "=r"(a[2]), "=r"(a[3])
                                 : "r"(addr));
                }
                uint32_t bf[8][2];
#pragma unroll
                for (int np = 0; np < 4; np++) {
                    const int row = np * 16 + (sub >> 1) * 8 + j8;
                    unsigned addr = smem_u32(Vc + row * FSTR + k8 + (sub & 1) * 4);
                    asm volatile("ldmatrix.sync.aligned.m8n8.x4.shared.b16 {%0,%1,%2,%3}, [%4];\n"
                                 : "=r"(bf[2*np][0]), "=r"(bf[2*np][1]),
                                   "=r"(bf[2*np+1][0]), "=r"(bf[2*np+1][1])
                                 : "r"(addr));
                }
#pragma unroll
                for (int nf = 0; nf < 8; nf++)
                    asm volatile(
                        "mma.sync.aligned.m16n8k8.row.col.f32.tf32.tf32.f32 "
                        "{%0,%1,%2,%3}, {%4,%5,%6,%7}, {%8,%9}, {%0,%1,%2,%3};\n"
                        : "+f"(O[nf][0]), "+f"(O[nf][1]),
                          "+f"(O[nf][2]), "+f"(O[nf][3])
                        : "r"(a[0]), "r"(a[1]), "r"(a[2]), "r"(a[3]),
                          "r"(bf[nf][0]), "r"(bf[nf][1]));
            }
        }
        __syncthreads();   // all reads of tile kb done before it is overwritten
    }

    // ---- epilogue: normalize, tf32-round, write g_y [b][t][h*64+d] ----
#pragma unroll
    for (int rr = 0; rr < 2; rr++) {
        const float inv = 1.f / l[rr];
        const int t = qi * QT + warp * 16 + g + rr * 8;
        float* dst = g_y + ((size_t)(b * TT + t)) * DD + h * 64;
#pragma unroll
        for (int nf = 0; nf < 8; nf++) {
            const int d0 = nf * 8 + 2 * tg;
            *(float2*)(dst + d0) =
                make_float2(rtf32(O[nf][rr*2] * inv),
                            rtf32(O[nf][rr*2+1] * inv));
        }
    }
}

// ---------------------------------------------------------------------------
extern "C" void kernel_launch(void* const* d_in, const int* in_sizes, int n_in,
                              void* d_out, int out_size)
{
    const float* x     = (const float*)d_in[0];
    const float* w_qkv = (const float*)d_in[1];
    const float* b_qkv = (const float*)d_in[2];
    const float* w_o   = (const float*)d_in[3];
    const float* b_o   = (const float*)d_in[4];
    float* out = (float*)d_out;

    const int gemm_smem  = 6 * SBUF * (int)sizeof(float);                 // 110592
    const int flash_smem = (QT + 4 * 64) * FSTR * (int)sizeof(float);     // 104448
    cudaFuncSetAttribute(gemm_tf32<0>, cudaFuncAttributeMaxDynamicSharedMemorySize, gemm_smem);
    cudaFuncSetAttribute(gemm_tf32<1>, cudaFuncAttributeMaxDynamicSharedMemorySize, gemm_smem);
    cudaFuncSetAttribute(flash_tc,     cudaFuncAttributeMaxDynamicSharedMemorySize, flash_smem);

    // Prep
    round_x_kernel<<<MROWS * DD / (256 * 4), 256>>>(x);
    {
        dim3 g1(3 * DD / 32, DD / 32);
        transpose_round_kernel<0><<<g1, 256>>>(w_qkv, DD, 3 * DD);
        dim3 g2(DD / 32, DD / 32);
        transpose_round_kernel<1><<<g2, 256>>>(w_o, DD, DD);
    }

    // QKV projection (tensor cores)
    {
        dim3 grid(3 * DD / 128, MROWS / 128);
        gemm_tf32<0><<<grid, 256, gemm_smem>>>(b_qkv, nullptr, 3 * DD);
    }
    // Flash attention (tensor cores)
    {
        dim3 grid(TT / QT, BB * HH);   // (16, 32)
        flash_tc<<<grid, 256, flash_smem>>>();
    }
    // Output projection (tensor cores)
    {
        dim3 grid(DD / 128, MROWS / 128);
        gemm_tf32<1><<<grid, 256, gemm_smem>>>(b_o, out, DD);
    }
}

// round 13
// speedup vs baseline: 5.3057x; 1.4607x over previous
#include <cuda_runtime.h>
#include <cuda_fp16.h>
#include <math.h>
#include <stdint.h>

#define BB 2
#define TT 2048
#define DD 1024
#define HH 16
#define HD 64
#define MROWS (BB*TT)   // 4096

// Scratch (allocation-free rule: device globals), all fp16 operands
__device__ __half g_q[BB*HH*TT*HD];    // [b][h][t][hd], pre-scaled by log2e/32
__device__ __half g_k[BB*HH*TT*HD];    // [b][h][t][hd]
__device__ __half g_v[BB*HH*TT*HD];    // [b][h][hd][t]  TRANSPOSED
__device__ __half g_x16[MROWS*DD];     // x as fp16
__device__ __half g_wqT[3*DD*DD];      // [3D][D] transposed w_qkv fp16
__device__ __half g_woT[DD*DD];        // [D][D]  transposed w_o  fp16
__device__ __half g_y16[MROWS*DD];     // attention out fp16 [b][t][h*64+hd]

#define NEG_INF __int_as_float(0xff800000)

__device__ __forceinline__ unsigned smem_u32(const void* p) {
    return (unsigned)__cvta_generic_to_shared(p);
}

// ---------------------------------------------------------------------------
// Prep: convert x to fp16
// ---------------------------------------------------------------------------
__global__ __launch_bounds__(256)
void conv_x_kernel(const float* __restrict__ x)
{
    int i = (blockIdx.x * 256 + threadIdx.x) * 4;
    float4 v = *(const float4*)(x + i);
    __half2 a, b;
    a = __floats2half2_rn(v.x, v.y);
    b = __floats2half2_rn(v.z, v.w);
    *(__half2*)(g_x16 + i)     = a;
    *(__half2*)(g_x16 + i + 2) = b;
}

// ---------------------------------------------------------------------------
// Prep: transpose + convert weights. dst[c][r] = fp16(src[r][c]); src RxC.
// ---------------------------------------------------------------------------
template<int WHICH>
__global__ __launch_bounds__(256)
void transpose_half_kernel(const float* __restrict__ src, int R, int C)
{
    __half* dst = (WHICH == 0) ? g_wqT : g_woT;
    __shared__ float tile[32][33];
    const int r0 = blockIdx.y * 32, c0 = blockIdx.x * 32;
    const int tx = threadIdx.x & 31, ty = threadIdx.x >> 5;
#pragma unroll
    for (int i = 0; i < 32; i += 8)
        tile[ty + i][tx] = src[(size_t)(r0 + ty + i) * C + c0 + tx];
    __syncthreads();
#pragma unroll
    for (int i = 0; i < 32; i += 8)
        dst[(size_t)(c0 + ty + i) * R + r0 + tx] = __float2half_rn(tile[tx][ty + i]);
}

// ---------------------------------------------------------------------------
// FP16 tensor-core GEMM: C[M,N] = A[M,K] @ Bt[N,K]^T + bias, fp32 accumulate.
// 128x128 tile, K-chunk 64, 8 warps (64x32 warp tiles), 3-stage cp.async.
// m16n8k16 f16 mma; smem row stride 72 halves (144B: conflict-free, 16B-aligned).
// MODE 0: A=g_x16, Bt=g_wqT -> scatter q (scaled)/k -> [B,H,T,HD], v -> [B,H,HD,T]
// MODE 1: A=g_y16, Bt=g_woT -> fp32 C row-major (final output)
// ---------------------------------------------------------------------------
#define SROWH 72
#define HBUF (128*SROWH)   // halves per tile buffer

template<int MODE>
__global__ __launch_bounds__(256, 2)
void gemm_fp16(const float* __restrict__ bias, float* __restrict__ C, int N)
{
    extern __shared__ __half hsm[];
    __half* Asm = hsm;              // 3 buffers
    __half* Bsm = hsm + 3 * HBUF;   // 3 buffers
    const int K = DD;

    const int tid  = threadIdx.x;
    const int lane = tid & 31, warp = tid >> 5;
    const int wm = warp >> 2;       // 0..1
    const int wn = warp & 3;        // 0..3
    const int bm = blockIdx.y * 128, bn = blockIdx.x * 128;

    const __half* Aeff = (MODE == 0) ? g_x16 : g_y16;
    const __half* Bt   = (MODE == 0) ? g_wqT : g_woT;

    float acc[4][4][4];
#pragma unroll
    for (int a = 0; a < 4; a++)
#pragma unroll
        for (int b = 0; b < 4; b++)
#pragma unroll
            for (int c = 0; c < 4; c++) acc[a][b][c] = 0.f;

    const int lm = tid >> 1;          // 0..127 row
    const int lq = (tid & 1) << 5;    // half-offset of 16B pair start (0 or 32)? no:
    // 64 halves per row = 8 x 16B chunks; 256 threads cover 128 rows x 2 chunks/thread iter
    // simpler: thread t handles row (t>>1), chunks (t&1)*4 .. +3

    auto copy_chunk = [&](int ck, int buf) {
        const __half* ag = Aeff + (size_t)bm * K + ck * 64;
        const __half* bg = Bt   + (size_t)bn * K + ck * 64;
        __half* as = Asm + buf * HBUF;
        __half* bs = Bsm + buf * HBUF;
        const int r = lm;            // 0..127
        const int q0 = (tid & 1) * 4;  // 16B-chunk index 0..3 or 4..7
#pragma unroll
        for (int qq = 0; qq < 4; qq++) {
            const int q = q0 + qq;   // 0..7
            asm volatile("cp.async.cg.shared.global [%0], [%1], 16;\n"
                         :: "r"(smem_u32(as + r * SROWH + q * 8)),
                            "l"(ag + (size_t)r * K + q * 8) : "memory");
            asm volatile("cp.async.cg.shared.global [%0], [%1], 16;\n"
                         :: "r"(smem_u32(bs + r * SROWH + q * 8)),
                            "l"(bg + (size_t)r * K + q * 8) : "memory");
        }
        asm volatile("cp.async.commit_group;\n" ::: "memory");
    };

    copy_chunk(0, 0);
    copy_chunk(1, 1);

    const int j8  = lane & 7;
    const int sub = lane >> 3;

    int cur = 0;
    const int NCK = K / 64;   // 16
    for (int ck = 0; ck < NCK; ck++) {
        if (ck < NCK - 1) { asm volatile("cp.async.wait_group 1;\n" ::: "memory"); }
        else             { asm volatile("cp.async.wait_group 0;\n" ::: "memory"); }
        __syncthreads();
        if (ck + 2 < NCK) {
            int pf = cur + 2; if (pf >= 3) pf -= 3;
            copy_chunk(ck + 2, pf);
        }

        const __half* as = Asm + cur * HBUF;
        const __half* bs = Bsm + cur * HBUF;

#pragma unroll
        for (int ks = 0; ks < 4; ks++) {          // 4 x k16 per 64-chunk
            const int k16 = ks * 16;
            uint32_t a[4][4];
#pragma unroll
            for (int mf = 0; mf < 4; mf++) {
                const int row = wm * 64 + mf * 16 + (sub & 1) * 8 + j8;
                const int col = k16 + (sub >> 1) * 8;
                unsigned addr = smem_u32(as + row * SROWH + col);
                asm volatile("ldmatrix.sync.aligned.m8n8.x4.shared.b16 {%0,%1,%2,%3}, [%4];\n"
                             : "=r"(a[mf][0]), "=r"(a[mf][1]), "=r"(a[mf][2]), "=r"(a[mf][3])
                             : "r"(addr));
            }
            uint32_t b[4][2];
#pragma unroll
            for (int np = 0; np < 2; np++) {      // covers n-tiles 2np, 2np+1
                const int row = wn * 32 + np * 16 + (sub >> 1) * 8 + j8;
                const int col = k16 + (sub & 1) * 8;
                unsigned addr = smem_u32(bs + row * SROWH + col);
                asm volatile("ldmatrix.sync.aligned.m8n8.x4.shared.b16 {%0,%1,%2,%3}, [%4];\n"
                             : "=r"(b[2*np][0]), "=r"(b[2*np][1]),
                               "=r"(b[2*np+1][0]), "=r"(b[2*np+1][1])
                             : "r"(addr));
            }
#pragma unroll
            for (int mf = 0; mf < 4; mf++)
#pragma unroll
                for (int nf = 0; nf < 4; nf++)
                    asm volatile(
                        "mma.sync.aligned.m16n8k16.row.col.f32.f16.f16.f32 "
                        "{%0,%1,%2,%3}, {%4,%5,%6,%7}, {%8,%9}, {%0,%1,%2,%3};\n"
                        : "+f"(acc[mf][nf][0]), "+f"(acc[mf][nf][1]),
                          "+f"(acc[mf][nf][2]), "+f"(acc[mf][nf][3])
                        : "r"(a[mf][0]), "r"(a[mf][1]), "r"(a[mf][2]), "r"(a[mf][3]),
                          "r"(b[nf][0]), "r"(b[nf][1]));
        }
        cur = (cur + 1 == 3) ? 0 : cur + 1;
    }

    // Epilogue
    const float qscale = 1.44269504088896340736f * 0.03125f;   // log2e / sqrt(1024)
    const int g  = lane >> 2;
    const int tg = lane & 3;
#pragma unroll
    for (int mf = 0; mf < 4; mf++) {
#pragma unroll
        for (int nf = 0; nf < 4; nf++) {
            const int col  = bn + wn * 32 + nf * 8 + 2 * tg;
            const float b0 = bias[col], b1 = bias[col + 1];
            const int row0 = bm + wm * 64 + mf * 16 + g;
            float v00 = acc[mf][nf][0] + b0, v01 = acc[mf][nf][1] + b1;
            float v10 = acc[mf][nf][2] + b0, v11 = acc[mf][nf][3] + b1;
            if (MODE == 0) {
                const int part = col >> 10;
                const int rem  = col & 1023;
                const int h    = rem >> 6;
                const int hd0  = rem & 63;
                if (part == 0) {   // q: fold in softmax scale
                    v00 *= qscale; v01 *= qscale; v10 *= qscale; v11 *= qscale;
                }
#pragma unroll
                for (int rr = 0; rr < 2; rr++) {
                    const int row = row0 + rr * 8;
                    const int bb = row >> 11;
                    const int t  = row & (TT - 1);
                    const float vx = rr ? v10 : v00;
                    const float vy = rr ? v11 : v01;
                    if (part == 2) {
                        __half* dst = g_v + ((size_t)((bb * HH + h) * HD + hd0)) * TT + t;
                        dst[0]  = __float2half_rn(vx);
                        dst[TT] = __float2half_rn(vy);
                    } else {
                        __half* dbase = (part == 0) ? g_q : g_k;
                        *(__half2*)(dbase + ((size_t)((bb * HH + h) * TT + t)) * HD + hd0)
                            = __floats2half2_rn(vx, vy);
                    }
                }
            } else {
                *(float2*)(C + (size_t)row0 * N + col)       = make_float2(v00, v01);
                *(float2*)(C + (size_t)(row0 + 8) * N + col) = make_float2(v10, v11);
            }
        }
    }
}

// ---------------------------------------------------------------------------
// FP16 tensor-core flash attention.
// 256 threads (8 warps x 16 q-rows), 128 q/block, kv tiles 64, double-buffered.
// Q pre-scaled (log2e/32) fp16; exp2-domain softmax; fp32 accumulators.
// ---------------------------------------------------------------------------
#define QT 128

__global__ __launch_bounds__(256, 2)
void flash_fp16()
{
    extern __shared__ __half fsm[];
    __half* Ps  = fsm;                     // [128][SROWH]  Q staging, then P
    __half* Ksm = fsm + QT * SROWH;        // 2 x [64][SROWH]
    __half* Vsm = Ksm + 2 * 64 * SROWH;    // 2 x [64][SROWH]  Vt[d][c]

    const int tid  = threadIdx.x;
    const int lane = tid & 31, warp = tid >> 5;
    const int j8 = lane & 7, sub = lane >> 3;
    const int g  = lane >> 2, tg  = lane & 3;
    const int qi = blockIdx.x;
    const int bh = blockIdx.y;
    const int b = bh >> 4, h = bh & 15;

    const __half* qg = g_q + ((size_t)bh * TT + qi * QT) * HD;
    const __half* kg = g_k + (size_t)bh * TT * HD;
    const __half* vg = g_v + (size_t)bh * HD * TT;

    // Stage Q via cp.async (already scaled in GEMM epilogue)
    {
        const int r = tid >> 1;            // 0..127
        const int q0 = (tid & 1) * 4;
#pragma unroll
        for (int qq = 0; qq < 4; qq++) {
            const int q = q0 + qq;
            asm volatile("cp.async.cg.shared.global [%0], [%1], 16;\n"
                         :: "r"(smem_u32(Ps + r * SROWH + q * 8)),
                            "l"(qg + (size_t)r * HD + q * 8) : "memory");
        }
        asm volatile("cp.async.commit_group;\n" ::: "memory");
    }

    auto copy_kv = [&](int kb, int buf) {
        __half* kd = Ksm + buf * (64 * SROWH);
        __half* vd = Vsm + buf * (64 * SROWH);
        const int r = tid >> 2;            // 0..63
        const int q = tid & 3;             // 2 chunks each of K and V? 64 halves = 8 chunks
#pragma unroll
        for (int qq = 0; qq < 2; qq++) {
            const int c = q * 2 + qq;      // 0..7
            asm volatile("cp.async.cg.shared.global [%0], [%1], 16;\n"
                         :: "r"(smem_u32(kd + r * SROWH + c * 8)),
                            "l"(kg + (size_t)(kb * 64 + r) * HD + c * 8) : "memory");
            asm volatile("cp.async.cg.shared.global [%0], [%1], 16;\n"
                         :: "r"(smem_u32(vd + r * SROWH + c * 8)),
                            "l"(vg + (size_t)r * TT + kb * 64 + c * 8) : "memory");
        }
        asm volatile("cp.async.commit_group;\n" ::: "memory");
    };

    copy_kv(0, 0);
    asm volatile("cp.async.wait_group 0;\n" ::: "memory");
    __syncthreads();

    // Q A-fragments (own-warp rows), then Ps is free for P
    uint32_t aq[4][4];
#pragma unroll
    for (int ks = 0; ks < 4; ks++) {
        const int row = warp * 16 + (sub & 1) * 8 + j8;
        const int col = ks * 16 + (sub >> 1) * 8;
        unsigned addr = smem_u32(Ps + row * SROWH + col);
        asm volatile("ldmatrix.sync.aligned.m8n8.x4.shared.b16 {%0,%1,%2,%3}, [%4];\n"
                     : "=r"(aq[ks][0]), "=r"(aq[ks][1]), "=r"(aq[ks][2]), "=r"(aq[ks][3])
                     : "r"(addr));
    }

    float O[8][4];
    float m[2] = {NEG_INF, NEG_INF}, l[2] = {0.f, 0.f};
#pragma unroll
    for (int nf = 0; nf < 8; nf++)
#pragma unroll
        for (int e = 0; e < 4; e++) O[nf][e] = 0.f;

    const int nkv = 2 * qi + 2;
    for (int kb = 0; kb < nkv; kb++) {
        const int cur = kb & 1;
        if (kb + 1 < nkv) {
            copy_kv(kb + 1, cur ^ 1);
            asm volatile("cp.async.wait_group 1;\n" ::: "memory");
        } else {
            asm volatile("cp.async.wait_group 0;\n" ::: "memory");
        }
        __syncthreads();

        const bool active = (kb * 64 <= qi * QT + warp * 16 + 15);
        if (active) {
            const __half* Kc = Ksm + cur * (64 * SROWH);
            const __half* Vc = Vsm + cur * (64 * SROWH);

            // ---- S = Q K^T (k = d, 4 x k16) ----
            float acc[8][4];
#pragma unroll
            for (int nf = 0; nf < 8; nf++)
#pragma unroll
                for (int e = 0; e < 4; e++) acc[nf][e] = 0.f;

#pragma unroll
            for (int ks = 0; ks < 4; ks++) {
                const int k16 = ks * 16;
                uint32_t bf[8][2];
#pragma unroll
                for (int np = 0; np < 4; np++) {
                    const int row = np * 16 + (sub >> 1) * 8 + j8;
                    const int col = k16 + (sub & 1) * 8;
                    unsigned addr = smem_u32(Kc + row * SROWH + col);
                    asm volatile("ldmatrix.sync.aligned.m8n8.x4.shared.b16 {%0,%1,%2,%3}, [%4];\n"
                                 : "=r"(bf[2*np][0]), "=r"(bf[2*np][1]),
                                   "=r"(bf[2*np+1][0]), "=r"(bf[2*np+1][1])
                                 : "r"(addr));
                }
#pragma unroll
                for (int nf = 0; nf < 8; nf++)
                    asm volatile(
                        "mma.sync.aligned.m16n8k16.row.col.f32.f16.f16.f32 "
                        "{%0,%1,%2,%3}, {%4,%5,%6,%7}, {%8,%9}, {%0,%1,%2,%3};\n"
                        : "+f"(acc[nf][0]), "+f"(acc[nf][1]),
                          "+f"(acc[nf][2]), "+f"(acc[nf][3])
                        : "r"(aq[ks][0]), "r"(aq[ks][1]), "r"(aq[ks][2]), "r"(aq[ks][3]),
                          "r"(bf[nf][0]), "r"(bf[nf][1]));
            }

            // ---- causal mask ----
            if (kb >= 2 * qi) {
                const int col0 = kb * 64 + 2 * tg;
                const int row0 = qi * QT + warp * 16 + g;
#pragma unroll
                for (int nf = 0; nf < 8; nf++)
#pragma unroll
                    for (int e = 0; e < 4; e++) {
                        const int row = row0 + (e >> 1) * 8;
                        const int col = col0 + nf * 8 + (e & 1);
                        if (col > row) acc[nf][e] = NEG_INF;
                    }
            }

            // ---- online softmax (exp2 domain) ----
#pragma unroll
            for (int rr = 0; rr < 2; rr++) {
                float rm = NEG_INF;
#pragma unroll
                for (int nf = 0; nf < 8; nf++)
                    rm = fmaxf(rm, fmaxf(acc[nf][rr*2], acc[nf][rr*2+1]));
                rm = fmaxf(rm, __shfl_xor_sync(0xffffffffu, rm, 1));
                rm = fmaxf(rm, __shfl_xor_sync(0xffffffffu, rm, 2));
                const float mo = m[rr];
                const float mn = fmaxf(mo, rm);
                const float corr = exp2f(mo - mn);
                m[rr] = mn;
                float rs = 0.f;
#pragma unroll
                for (int nf = 0; nf < 8; nf++) {
                    const float p0 = exp2f(acc[nf][rr*2]   - mn);
                    const float p1 = exp2f(acc[nf][rr*2+1] - mn);
                    acc[nf][rr*2]   = p0;
                    acc[nf][rr*2+1] = p1;
                    rs += p0 + p1;
                }
                rs += __shfl_xor_sync(0xffffffffu, rs, 1);
                rs += __shfl_xor_sync(0xffffffffu, rs, 2);
                l[rr] = l[rr] * corr + rs;
#pragma unroll
                for (int nf = 0; nf < 8; nf++) {
                    O[nf][rr*2]   *= corr;
                    O[nf][rr*2+1] *= corr;
                }
            }

            // ---- write P as fp16 (own-warp rows) ----
            {
                const int r0 = warp * 16 + g;
#pragma unroll
                for (int nf = 0; nf < 8; nf++) {
                    const int col = nf * 8 + 2 * tg;
                    *(__half2*)(Ps + r0 * SROWH + col) =
                        __floats2half2_rn(acc[nf][0], acc[nf][1]);
                    *(__half2*)(Ps + (r0 + 8) * SROWH + col) =
                        __floats2half2_rn(acc[nf][2], acc[nf][3]);
                }
            }
            __syncwarp();

            // ---- O += P @ V (k = kv, 4 x k16) ----
#pragma unroll
            for (int ks = 0; ks < 4; ks++) {
                const int k16 = ks * 16;
                uint32_t a[4];
                {
                    const int row = warp * 16 + (sub & 1) * 8 + j8;
                    const int col = k16 + (sub >> 1) * 8;
                    unsigned addr = smem_u32(Ps + row * SROWH + col);
                    asm volatile("ldmatrix.sync.aligned.m8n8.x4.shared.b16 {%0,%1,%2,%3}, [%4];\n"
                                 : "=r"(a[0]), "=r"(a[1]), "=r"(a[2]), "=r"(a[3])
                                 : "r"(addr));
                }
                uint32_t bf[8][2];
#pragma unroll
                for (int np = 0; np < 4; np++) {
                    const int row = np * 16 + (sub >> 1) * 8 + j8;
                    const int col = k16 + (sub & 1) * 8;
                    unsigned addr = smem_u32(Vc + row * SROWH + col);
                    asm volatile("ldmatrix.sync.aligned.m8n8.x4.shared.b16 {%0,%1,%2,%3}, [%4];\n"
                                 : "=r"(bf[2*np][0]), "=r"(bf[2*np][1]),
                                   "=r"(bf[2*np+1][0]), "=r"(bf[2*np+1][1])
                                 : "r"(addr));
                }
#pragma unroll
                for (int nf = 0; nf < 8; nf++)
                    asm volatile(
                        "mma.sync.aligned.m16n8k16.row.col.f32.f16.f16.f32 "
                        "{%0,%1,%2,%3}, {%4,%5,%6,%7}, {%8,%9}, {%0,%1,%2,%3};\n"
                        : "+f"(O[nf][0]), "+f"(O[nf][1]),
                          "+f"(O[nf][2]), "+f"(O[nf][3])
                        : "r"(a[0]), "r"(a[1]), "r"(a[2]), "r"(a[3]),
                          "r"(bf[nf][0]), "r"(bf[nf][1]));
            }
        }
        __syncthreads();
    }

    // ---- epilogue: normalize, fp16, write g_y16 [b][t][h*64+d] ----
#pragma unroll
    for (int rr = 0; rr < 2; rr++) {
        const float inv = 1.f / l[rr];
        const int t = qi * QT + warp * 16 + g + rr * 8;
        const size_t rowoff = (size_t)(b * TT + t) * DD + h * 64;
#pragma unroll
        for (int nf = 0; nf < 8; nf++) {
            const int d0 = nf * 8 + 2 * tg;
            *(__half2*)(g_y16 + rowoff + d0) =
                __floats2half2_rn(O[nf][rr*2] * inv, O[nf][rr*2+1] * inv);
        }
    }
}

// ---------------------------------------------------------------------------
extern "C" void kernel_launch(void* const* d_in, const int* in_sizes, int n_in,
                              void* d_out, int out_size)
{
    const float* x     = (const float*)d_in[0];
    const float* w_qkv = (const float*)d_in[1];
    const float* b_qkv = (const float*)d_in[2];
    const float* w_o   = (const float*)d_in[3];
    const float* b_o   = (const float*)d_in[4];
    float* out = (float*)d_out;

    const int gemm_smem  = 6 * HBUF * (int)sizeof(__half);                // 110592
    const int flash_smem = (QT + 4 * 64) * SROWH * (int)sizeof(__half);   // 55296
    cudaFuncSetAttribute(gemm_fp16<0>, cudaFuncAttributeMaxDynamicSharedMemorySize, gemm_smem);
    cudaFuncSetAttribute(gemm_fp16<1>, cudaFuncAttributeMaxDynamicSharedMemorySize, gemm_smem);
    cudaFuncSetAttribute(flash_fp16,   cudaFuncAttributeMaxDynamicSharedMemorySize, flash_smem);

    // Prep: convert x, transpose+convert weights
    conv_x_kernel<<<MROWS * DD / (256 * 4), 256>>>(x);
    {
        dim3 g1(3 * DD / 32, DD / 32);
        transpose_half_kernel<0><<<g1, 256>>>(w_qkv, DD, 3 * DD);
        dim3 g2(DD / 32, DD / 32);
        transpose_half_kernel<1><<<g2, 256>>>(w_o, DD, DD);
    }

    // QKV projection: [4096,1024] @ [1024,3072] -> q/k/v (fp16)
    {
        dim3 grid(3 * DD / 128, MROWS / 128);   // (24, 32)
        gemm_fp16<0><<<grid, 256, gemm_smem>>>(b_qkv, nullptr, 3 * DD);
    }
    // Flash attention (fp16 tensor cores)
    {
        dim3 grid(TT / QT, BB * HH);            // (16, 32)
        flash_fp16<<<grid, 256, flash_smem>>>();
    }
    // Output projection: [4096,1024] @ [1024,1024] + b_o -> fp32 out
    {
        dim3 grid(DD / 128, MROWS / 128);       // (8, 32)
        gemm_fp16<1><<<grid, 256, gemm_smem>>>(b_o, out, DD);
    }
}